// round 2
// baseline (speedup 1.0000x reference)
#include <cuda_runtime.h>
#include <math.h>

#define N_NODES  50000
#define N_EDGES  800000
#define N_GRAPHS 2500

// ---------------- scratch (device globals; no allocations allowed) ----------
__device__ __align__(256) float g_q[N_NODES * 256];
__device__ __align__(256) float g_k[N_NODES * 256];
__device__ __align__(256) float g_v[N_NODES * 256];
__device__ __align__(256) float g_skip[N_NODES * 256];
__device__ __align__(256) float g_h[N_NODES * 256];
__device__ __align__(256) float g_agg[N_NODES * 256];
__device__ __align__(256) float g_alpha[N_EDGES * 2];
__device__ __align__(256) float g_ex[N_EDGES * 2];
__device__ __align__(256) float g_amax[N_NODES * 2];
__device__ __align__(256) float g_denom[N_NODES * 2];
__device__ __align__(256) float g_cnt[N_GRAPHS];

// ---------------- helpers ----------------------------------------------------
__device__ __forceinline__ void atomicMaxFloat(float* addr, float val) {
    if (val >= 0.f)
        atomicMax((int*)addr, __float_as_int(val));
    else
        atomicMin((unsigned int*)addr, __float_as_uint(val));
}

// ---------------- GEMM: Y[N,M] = A[N,K] @ W[K,M] + bias  --------------------
// 128x64 tile, 256 threads, each thread 8x4 accumulators, BK=16.
__global__ __launch_bounds__(256) void gemm_bias_kernel(
    const float* __restrict__ A, const float* __restrict__ W,
    const float* __restrict__ bias, float* __restrict__ Y,
    int K, int M)
{
    __shared__ float As[16][129];
    __shared__ float Bs[16][64];

    const int t  = threadIdx.x;
    const int r0 = blockIdx.y * 128;
    const int c0 = blockIdx.x * 64;
    const int tm = t >> 4;        // 0..15 -> rows tm*8 .. tm*8+7
    const int tn = t & 15;        // 0..15 -> cols tn*4 .. tn*4+3

    float acc[8][4];
#pragma unroll
    for (int j = 0; j < 8; j++)
#pragma unroll
        for (int i = 0; i < 4; i++) acc[j][i] = 0.f;

    for (int kt = 0; kt < K; kt += 16) {
        // load A tile: 128 rows x 16 k  (2048 elems / 256 thr = 8 each)
#pragma unroll
        for (int i = 0; i < 8; i++) {
            int e = t + i * 256;
            int kk = e & 15, m = e >> 4;
            int row = r0 + m;
            As[kk][m] = (row < N_NODES) ? A[(long)row * K + kt + kk] : 0.f;
        }
        // load W tile: 16 k x 64 cols (1024 elems / 256 thr = 4 each)
#pragma unroll
        for (int i = 0; i < 4; i++) {
            int e = t + i * 256;
            int kk = e >> 6, n = e & 63;
            Bs[kk][n] = W[(kt + kk) * M + c0 + n];
        }
        __syncthreads();
#pragma unroll
        for (int kk = 0; kk < 16; kk++) {
            float4 b = *(const float4*)&Bs[kk][tn * 4];
#pragma unroll
            for (int j = 0; j < 8; j++) {
                float a = As[kk][tm * 8 + j];
                acc[j][0] = fmaf(a, b.x, acc[j][0]);
                acc[j][1] = fmaf(a, b.y, acc[j][1]);
                acc[j][2] = fmaf(a, b.z, acc[j][2]);
                acc[j][3] = fmaf(a, b.w, acc[j][3]);
            }
        }
        __syncthreads();
    }

    int col = c0 + tn * 4;
    float4 bv = *(const float4*)&bias[col];
#pragma unroll
    for (int j = 0; j < 8; j++) {
        int row = r0 + tm * 8 + j;
        if (row < N_NODES) {
            float4 o;
            o.x = acc[j][0] + bv.x;
            o.y = acc[j][1] + bv.y;
            o.z = acc[j][2] + bv.z;
            o.w = acc[j][3] + bv.w;
            *(float4*)&Y[(long)row * M + col] = o;
        }
    }
}

// ---------------- per-layer init ---------------------------------------------
__global__ __launch_bounds__(256) void init_layer_kernel() {
    int i = blockIdx.x * blockDim.x + threadIdx.x;
    if (i < N_NODES * 2) { g_amax[i] = -INFINITY; g_denom[i] = 0.f; }
    if (i < N_NODES * 256) g_agg[i] = 0.f;
}

// ---------------- edge pass 1: alpha + segment max ---------------------------
// one warp per edge, both heads.  edge_index is int32 (JAX x64 disabled).
__global__ __launch_bounds__(256) void edge_alpha_kernel(
    const int* __restrict__ ei, const float* __restrict__ ea,
    const float* __restrict__ We)
{
    int e = blockIdx.x * 8 + (threadIdx.x >> 5);
    if (e >= N_EDGES) return;
    int lane = threadIdx.x & 31;
    int src = ei[e];
    int dst = ei[N_EDGES + e];
    float w = ea[e];
    const float* qd = g_q + (size_t)dst * 256;
    const float* ks = g_k + (size_t)src * 256;
#pragma unroll
    for (int h = 0; h < 2; h++) {
        int off = h * 128 + lane * 4;
        float4 qv = *(const float4*)(qd + off);
        float4 kv = *(const float4*)(ks + off);
        float4 ev = *(const float4*)(We + off);
        float s = qv.x * fmaf(w, ev.x, kv.x)
                + qv.y * fmaf(w, ev.y, kv.y)
                + qv.z * fmaf(w, ev.z, kv.z)
                + qv.w * fmaf(w, ev.w, kv.w);
#pragma unroll
        for (int o = 16; o; o >>= 1) s += __shfl_xor_sync(0xffffffffu, s, o);
        s *= 0.08838834764831845f;  // 1/sqrt(128)
        if (lane == 0) {
            g_alpha[e * 2 + h] = s;
            atomicMaxFloat(&g_amax[dst * 2 + h], s);
        }
    }
}

// ---------------- edge pass 2: exp + segment sum ------------------------------
__global__ __launch_bounds__(256) void edge_softmax_kernel(
    const int* __restrict__ ei)
{
    int i = blockIdx.x * blockDim.x + threadIdx.x;
    if (i >= 2 * N_EDGES) return;
    int e = i >> 1, h = i & 1;
    int dst = ei[N_EDGES + e];
    float v = expf(g_alpha[i] - g_amax[dst * 2 + h]);
    g_ex[i] = v;
    atomicAdd(&g_denom[dst * 2 + h], v);
}

// ---------------- edge pass 3: weighted scatter -------------------------------
__global__ __launch_bounds__(256) void edge_scatter_kernel(
    const int* __restrict__ ei, const float* __restrict__ ea,
    const float* __restrict__ We)
{
    int e = blockIdx.x * 8 + (threadIdx.x >> 5);
    if (e >= N_EDGES) return;
    int lane = threadIdx.x & 31;
    int src = ei[e];
    int dst = ei[N_EDGES + e];
    float w = ea[e];
    const float* vs = g_v + (size_t)src * 256;
    float* ad = g_agg + (size_t)dst * 256;
#pragma unroll
    for (int h = 0; h < 2; h++) {
        float wt = g_ex[e * 2 + h] / g_denom[dst * 2 + h];
        int off = h * 128 + lane * 4;
        float4 vv = *(const float4*)(vs + off);
        float4 ev = *(const float4*)(We + off);
        atomicAdd(ad + off + 0, wt * fmaf(w, ev.x, vv.x));
        atomicAdd(ad + off + 1, wt * fmaf(w, ev.y, vv.y));
        atomicAdd(ad + off + 2, wt * fmaf(w, ev.z, vv.z));
        atomicAdd(ad + off + 3, wt * fmaf(w, ev.w, vv.w));
    }
}

// ---------------- layer combines ----------------------------------------------
__global__ __launch_bounds__(256) void combine1_kernel() {
    int i = blockIdx.x * blockDim.x + threadIdx.x;
    if (i >= N_NODES * 256) return;
    g_h[i] = fmaxf(g_agg[i] + g_skip[i], 0.f);
}

__global__ __launch_bounds__(256) void combine2_kernel() {
    int i = blockIdx.x * blockDim.x + threadIdx.x;
    if (i >= N_NODES * 128) return;
    int n = i >> 7, c = i & 127;
    float m = 0.5f * (g_agg[n * 256 + c] + g_agg[n * 256 + 128 + c]);
    g_h[i] = m + g_skip[n * 128 + c];   // g_skip holds layer2 skip [N,128]
}

// ---------------- pooling ------------------------------------------------------
__global__ __launch_bounds__(256) void pool_zero_kernel(float* __restrict__ out) {
    int i = blockIdx.x * blockDim.x + threadIdx.x;
    if (i < N_GRAPHS * 128) out[i] = 0.f;
    if (i < N_GRAPHS) g_cnt[i] = 0.f;
}

__global__ __launch_bounds__(128) void pool_sum_kernel(
    const int* __restrict__ batch, float* __restrict__ out)
{
    int n = blockIdx.x;
    int c = threadIdx.x;
    int g = batch[n];
    atomicAdd(&out[(size_t)g * 128 + c], g_h[(size_t)n * 128 + c]);
    if (c == 0) atomicAdd(&g_cnt[g], 1.f);
}

__global__ __launch_bounds__(256) void pool_div_kernel(float* __restrict__ out) {
    int i = blockIdx.x * blockDim.x + threadIdx.x;
    if (i >= N_GRAPHS * 128) return;
    out[i] /= fmaxf(g_cnt[i >> 7], 1.f);
}

// ---------------- launch -------------------------------------------------------
extern "C" void kernel_launch(void* const* d_in, const int* in_sizes, int n_in,
                              void* d_out, int out_size)
{
    const float* x     = (const float*)d_in[0];
    const int*   ei    = (const int*)d_in[1];     // int32: JAX x64 disabled
    const int*   batch = (const int*)d_in[2];
    const float* ea    = (const float*)d_in[3];
    const float* Wq1 = (const float*)d_in[4];
    const float* bq1 = (const float*)d_in[5];
    const float* Wk1 = (const float*)d_in[6];
    const float* bk1 = (const float*)d_in[7];
    const float* Wv1 = (const float*)d_in[8];
    const float* bv1 = (const float*)d_in[9];
    const float* We1 = (const float*)d_in[10];
    const float* Ws1 = (const float*)d_in[11];
    const float* bs1 = (const float*)d_in[12];
    const float* Wq2 = (const float*)d_in[13];
    const float* bq2 = (const float*)d_in[14];
    const float* Wk2 = (const float*)d_in[15];
    const float* bk2 = (const float*)d_in[16];
    const float* Wv2 = (const float*)d_in[17];
    const float* bv2 = (const float*)d_in[18];
    const float* We2 = (const float*)d_in[19];
    const float* Ws2 = (const float*)d_in[20];
    const float* bs2 = (const float*)d_in[21];
    float* out = (float*)d_out;

    float *pq, *pk, *pv, *pskip, *ph;
    cudaGetSymbolAddress((void**)&pq,    g_q);
    cudaGetSymbolAddress((void**)&pk,    g_k);
    cudaGetSymbolAddress((void**)&pv,    g_v);
    cudaGetSymbolAddress((void**)&pskip, g_skip);
    cudaGetSymbolAddress((void**)&ph,    g_h);

    const int ROWB = (N_NODES + 127) / 128;           // 391
    dim3 g256(4, ROWB), g128(2, ROWB);

    const int EWB = (N_EDGES + 7) / 8;                // warp-per-edge blocks
    const int NC256 = (N_NODES * 256 + 255) / 256;
    const int NC128 = (N_NODES * 128 + 255) / 256;
    const int ESM   = (2 * N_EDGES + 255) / 256;
    const int PZ    = (N_GRAPHS * 128 + 255) / 256;

    // ---------------- layer 1 (in=128, concat heads) ----------------
    gemm_bias_kernel<<<g256, 256>>>(x, Wq1, bq1, pq, 128, 256);
    gemm_bias_kernel<<<g256, 256>>>(x, Wk1, bk1, pk, 128, 256);
    gemm_bias_kernel<<<g256, 256>>>(x, Wv1, bv1, pv, 128, 256);
    gemm_bias_kernel<<<g256, 256>>>(x, Ws1, bs1, pskip, 128, 256);
    init_layer_kernel<<<NC256, 256>>>();
    edge_alpha_kernel<<<EWB, 256>>>(ei, ea, We1);
    edge_softmax_kernel<<<ESM, 256>>>(ei);
    edge_scatter_kernel<<<EWB, 256>>>(ei, ea, We1);
    combine1_kernel<<<NC256, 256>>>();

    // ---------------- layer 2 (in=256, mean heads) -------------------
    gemm_bias_kernel<<<g256, 256>>>(ph, Wq2, bq2, pq, 256, 256);
    gemm_bias_kernel<<<g256, 256>>>(ph, Wk2, bk2, pk, 256, 256);
    gemm_bias_kernel<<<g256, 256>>>(ph, Wv2, bv2, pv, 256, 256);
    gemm_bias_kernel<<<g128, 256>>>(ph, Ws2, bs2, pskip, 256, 128);
    init_layer_kernel<<<NC256, 256>>>();
    edge_alpha_kernel<<<EWB, 256>>>(ei, ea, We2);
    edge_softmax_kernel<<<ESM, 256>>>(ei);
    edge_scatter_kernel<<<EWB, 256>>>(ei, ea, We2);
    combine2_kernel<<<NC128, 256>>>();

    // ---------------- global mean pool --------------------------------
    pool_zero_kernel<<<PZ, 256>>>(out);
    pool_sum_kernel<<<N_NODES, 128>>>(batch, out);
    pool_div_kernel<<<PZ, 256>>>(out);
}

// round 3
// speedup vs baseline: 2.3762x; 2.3762x over previous
#include <cuda_runtime.h>
#include <math.h>

#define N_NODES  50000
#define N_EDGES  800000
#define N_GRAPHS 2500

// ---------------- scratch (device globals; no allocations allowed) ----------
__device__ __align__(256) float g_q[N_NODES * 256];
__device__ __align__(256) float g_k[N_NODES * 256];
__device__ __align__(256) float g_v[N_NODES * 256];
__device__ __align__(256) float g_skip[N_NODES * 256];
__device__ __align__(256) float g_h[N_NODES * 256];
__device__ __align__(256) float g_alpha[N_EDGES * 2];
__device__ __align__(256) float g_cw[N_EDGES];
__device__ __align__(256) int   g_csrc[N_EDGES];
__device__ __align__(256) int   g_rowptr[N_NODES + 1];
__device__ __align__(256) int   g_wof[N_NODES];
__device__ __align__(256) float g_cnt[N_GRAPHS];

// =============== GEMM: Y[N,M] = A[N,K] @ W[K,M] + bias ======================
// 128x128 tile, 256 threads, 8x8 accumulators, BK=16.
__global__ __launch_bounds__(256, 2) void gemm_bias_kernel(
    const float* __restrict__ A, const float* __restrict__ W,
    const float* __restrict__ bias, float* __restrict__ Y,
    int K, int M)
{
    __shared__ float As[16][132];
    __shared__ float Bs[16][132];

    const int t  = threadIdx.x;
    const int r0 = blockIdx.y * 128;
    const int c0 = blockIdx.x * 128;
    const int tm = t >> 4;        // 0..15 -> rows tm*8 .. +7
    const int tn = t & 15;        // 0..15 -> cols tn*8 .. +7

    float acc[8][8];
#pragma unroll
    for (int j = 0; j < 8; j++)
#pragma unroll
        for (int i = 0; i < 8; i++) acc[j][i] = 0.f;

    for (int kt = 0; kt < K; kt += 16) {
        // A tile: 128 rows x 16 k; 512 float4 loads, 2 per thread (transposed store)
#pragma unroll
        for (int i = 0; i < 2; i++) {
            int fid = t + i * 256;          // 0..511
            int m   = fid >> 2;             // 0..127
            int kk  = (fid & 3) * 4;        // 0,4,8,12
            int row = r0 + m;
            float4 av = make_float4(0.f, 0.f, 0.f, 0.f);
            if (row < N_NODES)
                av = *(const float4*)&A[(size_t)row * K + kt + kk];
            As[kk + 0][m] = av.x;
            As[kk + 1][m] = av.y;
            As[kk + 2][m] = av.z;
            As[kk + 3][m] = av.w;
        }
        // B tile: 16 k x 128 cols; 512 float4 loads, 2 per thread
#pragma unroll
        for (int i = 0; i < 2; i++) {
            int fid = t + i * 256;
            int kk  = fid >> 5;             // 0..15
            int c   = (fid & 31) * 4;       // 0..124
            float4 wv = *(const float4*)&W[(size_t)(kt + kk) * M + c0 + c];
            *(float4*)&Bs[kk][c] = wv;
        }
        __syncthreads();
#pragma unroll
        for (int kk = 0; kk < 16; kk++) {
            float4 a0 = *(const float4*)&As[kk][tm * 8];
            float4 a1 = *(const float4*)&As[kk][tm * 8 + 4];
            float4 b0 = *(const float4*)&Bs[kk][tn * 8];
            float4 b1 = *(const float4*)&Bs[kk][tn * 8 + 4];
            float ar[8] = {a0.x, a0.y, a0.z, a0.w, a1.x, a1.y, a1.z, a1.w};
            float br[8] = {b0.x, b0.y, b0.z, b0.w, b1.x, b1.y, b1.z, b1.w};
#pragma unroll
            for (int j = 0; j < 8; j++)
#pragma unroll
                for (int i = 0; i < 8; i++)
                    acc[j][i] = fmaf(ar[j], br[i], acc[j][i]);
        }
        __syncthreads();
    }

    int colb = c0 + tn * 8;
    float4 bv0 = *(const float4*)&bias[colb];
    float4 bv1 = *(const float4*)&bias[colb + 4];
#pragma unroll
    for (int j = 0; j < 8; j++) {
        int row = r0 + tm * 8 + j;
        if (row < N_NODES) {
            float4 o0, o1;
            o0.x = acc[j][0] + bv0.x; o0.y = acc[j][1] + bv0.y;
            o0.z = acc[j][2] + bv0.z; o0.w = acc[j][3] + bv0.w;
            o1.x = acc[j][4] + bv1.x; o1.y = acc[j][5] + bv1.y;
            o1.z = acc[j][6] + bv1.z; o1.w = acc[j][7] + bv1.w;
            *(float4*)&Y[(size_t)row * M + colb]     = o0;
            *(float4*)&Y[(size_t)row * M + colb + 4] = o1;
        }
    }
}

// =============== CSR build ====================================================
__global__ __launch_bounds__(256) void zero_wof_kernel() {
    int i = blockIdx.x * blockDim.x + threadIdx.x;
    if (i < N_NODES) g_wof[i] = 0;
}

__global__ __launch_bounds__(256) void hist_kernel(const int* __restrict__ ei) {
    int e = blockIdx.x * blockDim.x + threadIdx.x;
    if (e < N_EDGES) atomicAdd(&g_wof[ei[N_EDGES + e]], 1);
}

__global__ __launch_bounds__(1024) void scan_kernel() {
    __shared__ int sb[2][1024];
    int t = threadIdx.x;
    int carry = 0;
    for (int base = 0; base < N_NODES; base += 1024) {
        int i = base + t;
        int v = (i < N_NODES) ? g_wof[i] : 0;
        int pin = 0;
        sb[0][t] = v;
        __syncthreads();
#pragma unroll
        for (int off = 1; off < 1024; off <<= 1) {
            int x = sb[pin][t];
            if (t >= off) x += sb[pin][t - off];
            sb[pin ^ 1][t] = x;
            __syncthreads();
            pin ^= 1;
        }
        int incl = sb[pin][t];
        int tot  = sb[pin][1023];
        int excl = incl - v + carry;
        if (i < N_NODES) { g_rowptr[i] = excl; g_wof[i] = excl; }
        carry += tot;
        __syncthreads();
    }
    if (t == 0) g_rowptr[N_NODES] = carry;
}

__global__ __launch_bounds__(256) void csr_scatter_kernel(
    const int* __restrict__ ei, const float* __restrict__ ea)
{
    int e = blockIdx.x * blockDim.x + threadIdx.x;
    if (e >= N_EDGES) return;
    int src = ei[e];
    int dst = ei[N_EDGES + e];
    int pos = atomicAdd(&g_wof[dst], 1);
    g_csrc[pos] = src;
    g_cw[pos]   = ea[e];
}

// =============== per-node attention (warp per node, CSR) ======================
// CONCAT=1: out[N,256] = relu(attn + skip[N,256])
// CONCAT=0: out[N,128] = mean_heads(attn) + skip[N,128]
template <int CONCAT>
__global__ __launch_bounds__(256) void node_attn_kernel(
    const float* __restrict__ q, const float* __restrict__ k,
    const float* __restrict__ v, const float* __restrict__ skip,
    const float* __restrict__ We, float* __restrict__ out)
{
    int n = blockIdx.x * 8 + (threadIdx.x >> 5);
    if (n >= N_NODES) return;
    int lane = threadIdx.x & 31;
    int beg = g_rowptr[n], end = g_rowptr[n + 1];
    int off0 = lane * 4, off1 = 128 + lane * 4;

    const float* qr = q + (size_t)n * 256;
    float4 q0 = *(const float4*)(qr + off0);
    float4 q1 = *(const float4*)(qr + off1);
    float4 e0 = *(const float4*)(We + off0);
    float4 e1 = *(const float4*)(We + off1);

    const float scale = 0.08838834764831845f;  // 1/sqrt(128)

    // pass 1: alpha + max
    float m0 = -INFINITY, m1 = -INFINITY;
    for (int p = beg; p < end; p++) {
        int s = g_csrc[p];
        float w = g_cw[p];
        const float* kr = k + (size_t)s * 256;
        float4 k0 = *(const float4*)(kr + off0);
        float4 k1 = *(const float4*)(kr + off1);
        float s0 = q0.x * fmaf(w, e0.x, k0.x) + q0.y * fmaf(w, e0.y, k0.y)
                 + q0.z * fmaf(w, e0.z, k0.z) + q0.w * fmaf(w, e0.w, k0.w);
        float s1 = q1.x * fmaf(w, e1.x, k1.x) + q1.y * fmaf(w, e1.y, k1.y)
                 + q1.z * fmaf(w, e1.z, k1.z) + q1.w * fmaf(w, e1.w, k1.w);
#pragma unroll
        for (int o = 16; o; o >>= 1) {
            s0 += __shfl_xor_sync(0xffffffffu, s0, o);
            s1 += __shfl_xor_sync(0xffffffffu, s1, o);
        }
        s0 *= scale; s1 *= scale;
        if (lane == 0) { g_alpha[2 * p] = s0; g_alpha[2 * p + 1] = s1; }
        m0 = fmaxf(m0, s0);
        m1 = fmaxf(m1, s1);
    }

    // pass 2: exp weights + weighted v accumulation (registers, no atomics)
    float d0 = 0.f, d1 = 0.f;
    float4 a0 = make_float4(0.f, 0.f, 0.f, 0.f);
    float4 a1 = make_float4(0.f, 0.f, 0.f, 0.f);
    for (int p = beg; p < end; p++) {
        int s = g_csrc[p];
        float w = g_cw[p];
        float x0 = expf(g_alpha[2 * p]     - m0);
        float x1 = expf(g_alpha[2 * p + 1] - m1);
        d0 += x0; d1 += x1;
        const float* vr = v + (size_t)s * 256;
        float4 v0 = *(const float4*)(vr + off0);
        float4 v1 = *(const float4*)(vr + off1);
        a0.x += x0 * fmaf(w, e0.x, v0.x);
        a0.y += x0 * fmaf(w, e0.y, v0.y);
        a0.z += x0 * fmaf(w, e0.z, v0.z);
        a0.w += x0 * fmaf(w, e0.w, v0.w);
        a1.x += x1 * fmaf(w, e1.x, v1.x);
        a1.y += x1 * fmaf(w, e1.y, v1.y);
        a1.z += x1 * fmaf(w, e1.z, v1.z);
        a1.w += x1 * fmaf(w, e1.w, v1.w);
    }
    float r0 = d0 > 0.f ? 1.f / d0 : 0.f;
    float r1 = d1 > 0.f ? 1.f / d1 : 0.f;
    a0.x *= r0; a0.y *= r0; a0.z *= r0; a0.w *= r0;
    a1.x *= r1; a1.y *= r1; a1.z *= r1; a1.w *= r1;

    if (CONCAT) {
        const float* sr = skip + (size_t)n * 256;
        float4 s0 = *(const float4*)(sr + off0);
        float4 s1 = *(const float4*)(sr + off1);
        float4 o0, o1;
        o0.x = fmaxf(a0.x + s0.x, 0.f); o0.y = fmaxf(a0.y + s0.y, 0.f);
        o0.z = fmaxf(a0.z + s0.z, 0.f); o0.w = fmaxf(a0.w + s0.w, 0.f);
        o1.x = fmaxf(a1.x + s1.x, 0.f); o1.y = fmaxf(a1.y + s1.y, 0.f);
        o1.z = fmaxf(a1.z + s1.z, 0.f); o1.w = fmaxf(a1.w + s1.w, 0.f);
        *(float4*)(out + (size_t)n * 256 + off0) = o0;
        *(float4*)(out + (size_t)n * 256 + off1) = o1;
    } else {
        float4 sk = *(const float4*)(skip + (size_t)n * 128 + off0);
        float4 o;
        o.x = 0.5f * (a0.x + a1.x) + sk.x;
        o.y = 0.5f * (a0.y + a1.y) + sk.y;
        o.z = 0.5f * (a0.z + a1.z) + sk.z;
        o.w = 0.5f * (a0.w + a1.w) + sk.w;
        *(float4*)(out + (size_t)n * 128 + off0) = o;
    }
}

// =============== pooling =======================================================
__global__ __launch_bounds__(256) void pool_zero_kernel(float* __restrict__ out) {
    int i = blockIdx.x * blockDim.x + threadIdx.x;
    if (i < N_GRAPHS * 128) out[i] = 0.f;
    if (i < N_GRAPHS) g_cnt[i] = 0.f;
}

__global__ __launch_bounds__(128) void pool_sum_kernel(
    const int* __restrict__ batch, const float* __restrict__ h,
    float* __restrict__ out)
{
    int n = blockIdx.x;
    int c = threadIdx.x;
    int g = batch[n];
    atomicAdd(&out[(size_t)g * 128 + c], h[(size_t)n * 128 + c]);
    if (c == 0) atomicAdd(&g_cnt[g], 1.f);
}

__global__ __launch_bounds__(256) void pool_div_kernel(float* __restrict__ out) {
    int i = blockIdx.x * blockDim.x + threadIdx.x;
    if (i >= N_GRAPHS * 128) return;
    out[i] /= fmaxf(g_cnt[i >> 7], 1.f);
}

// =============== launch =========================================================
extern "C" void kernel_launch(void* const* d_in, const int* in_sizes, int n_in,
                              void* d_out, int out_size)
{
    const float* x     = (const float*)d_in[0];
    const int*   ei    = (const int*)d_in[1];     // int32 (JAX x64 disabled)
    const int*   batch = (const int*)d_in[2];
    const float* ea    = (const float*)d_in[3];
    const float* Wq1 = (const float*)d_in[4];
    const float* bq1 = (const float*)d_in[5];
    const float* Wk1 = (const float*)d_in[6];
    const float* bk1 = (const float*)d_in[7];
    const float* Wv1 = (const float*)d_in[8];
    const float* bv1 = (const float*)d_in[9];
    const float* We1 = (const float*)d_in[10];
    const float* Ws1 = (const float*)d_in[11];
    const float* bs1 = (const float*)d_in[12];
    const float* Wq2 = (const float*)d_in[13];
    const float* bq2 = (const float*)d_in[14];
    const float* Wk2 = (const float*)d_in[15];
    const float* bk2 = (const float*)d_in[16];
    const float* Wv2 = (const float*)d_in[17];
    const float* bv2 = (const float*)d_in[18];
    const float* We2 = (const float*)d_in[19];
    const float* Ws2 = (const float*)d_in[20];
    const float* bs2 = (const float*)d_in[21];
    float* out = (float*)d_out;

    float *pq, *pk, *pv, *pskip, *ph;
    cudaGetSymbolAddress((void**)&pq,    g_q);
    cudaGetSymbolAddress((void**)&pk,    g_k);
    cudaGetSymbolAddress((void**)&pv,    g_v);
    cudaGetSymbolAddress((void**)&pskip, g_skip);
    cudaGetSymbolAddress((void**)&ph,    g_h);

    const int ROWB = (N_NODES + 127) / 128;           // 391
    dim3 gm256(2, ROWB), gm128(1, ROWB);

    const int EB  = (N_EDGES + 255) / 256;
    const int NB  = (N_NODES + 255) / 256;
    const int NWB = (N_NODES + 7) / 8;                // warp-per-node blocks
    const int PZ  = (N_GRAPHS * 128 + 255) / 256;

    // ---- CSR build (shared by both layers) ----
    zero_wof_kernel<<<NB, 256>>>();
    hist_kernel<<<EB, 256>>>(ei);
    scan_kernel<<<1, 1024>>>();
    csr_scatter_kernel<<<EB, 256>>>(ei, ea);

    // ---- layer 1 (in=128, concat heads) ----
    gemm_bias_kernel<<<gm256, 256>>>(x, Wq1, bq1, pq, 128, 256);
    gemm_bias_kernel<<<gm256, 256>>>(x, Wk1, bk1, pk, 128, 256);
    gemm_bias_kernel<<<gm256, 256>>>(x, Wv1, bv1, pv, 128, 256);
    gemm_bias_kernel<<<gm256, 256>>>(x, Ws1, bs1, pskip, 128, 256);
    node_attn_kernel<1><<<NWB, 256>>>(pq, pk, pv, pskip, We1, ph);

    // ---- layer 2 (in=256, mean heads) ----
    gemm_bias_kernel<<<gm256, 256>>>(ph, Wq2, bq2, pq, 256, 256);
    gemm_bias_kernel<<<gm256, 256>>>(ph, Wk2, bk2, pk, 256, 256);
    gemm_bias_kernel<<<gm256, 256>>>(ph, Wv2, bv2, pv, 256, 256);
    gemm_bias_kernel<<<gm128, 256>>>(ph, Ws2, bs2, pskip, 256, 128);
    node_attn_kernel<0><<<NWB, 256>>>(pq, pk, pv, pskip, We2, ph);

    // ---- global mean pool ----
    pool_zero_kernel<<<PZ, 256>>>(out);
    pool_sum_kernel<<<N_NODES, 128>>>(batch, ph, out);
    pool_div_kernel<<<PZ, 256>>>(out);
}

// round 5
// speedup vs baseline: 3.3874x; 1.4255x over previous
#include <cuda_runtime.h>
#include <cuda_bf16.h>
#include <math.h>
#include <stdint.h>

#define N_NODES  50000
#define N_EDGES  800000
#define N_GRAPHS 2500

// ---------------- scratch (device globals; no allocations allowed) ----------
__device__ __align__(256) float g_q[N_NODES * 256];
__device__ __align__(256) float g_k[N_NODES * 256];
__device__ __align__(256) float g_v[N_NODES * 256];
__device__ __align__(256) float g_skip[N_NODES * 256];
__device__ __align__(256) float g_h[N_NODES * 256];
__device__ __align__(256) float g_alpha[N_EDGES * 2];
__device__ __align__(256) float g_cw[N_EDGES];
__device__ __align__(256) int   g_csrc[N_EDGES];
__device__ __align__(256) int   g_rowptr[N_NODES + 1];
__device__ __align__(256) int   g_wof[N_NODES];
__device__ __align__(256) float g_cnt[N_GRAPHS];

// ================= warp-MMA helpers (sm_80+ path, no 'a' features) ==========
__device__ __forceinline__ uint32_t smem_u32(const void* p) {
    uint32_t a;
    asm("{ .reg .u64 t; cvta.to.shared.u64 t, %1; cvt.u32.u64 %0, t; }"
        : "=r"(a) : "l"(p));
    return a;
}

__device__ __forceinline__ void ldsm_x4(uint32_t r[4], uint32_t addr) {
    asm volatile("ldmatrix.sync.aligned.m8n8.x4.shared.b16 {%0,%1,%2,%3}, [%4];"
        : "=r"(r[0]), "=r"(r[1]), "=r"(r[2]), "=r"(r[3]) : "r"(addr));
}
__device__ __forceinline__ void ldsm_x4_t(uint32_t r[4], uint32_t addr) {
    asm volatile("ldmatrix.sync.aligned.m8n8.x4.trans.shared.b16 {%0,%1,%2,%3}, [%4];"
        : "=r"(r[0]), "=r"(r[1]), "=r"(r[2]), "=r"(r[3]) : "r"(addr));
}

__device__ __forceinline__ void mma16816(float d[4], const uint32_t a[4],
                                         const uint32_t b[2]) {
    asm volatile(
        "mma.sync.aligned.m16n8k16.row.col.f32.bf16.bf16.f32 "
        "{%0,%1,%2,%3}, {%4,%5,%6,%7}, {%8,%9}, {%0,%1,%2,%3};"
        : "+f"(d[0]), "+f"(d[1]), "+f"(d[2]), "+f"(d[3])
        : "r"(a[0]), "r"(a[1]), "r"(a[2]), "r"(a[3]), "r"(b[0]), "r"(b[1]));
}

// fp32 -> (hi, lo) bf16x4 pairs stored as uint2
__device__ __forceinline__ void cvt_split_store(
    __nv_bfloat16* hi, __nv_bfloat16* lo, float4 v)
{
    __nv_bfloat16 h0 = __float2bfloat16(v.x);
    __nv_bfloat16 h1 = __float2bfloat16(v.y);
    __nv_bfloat16 h2 = __float2bfloat16(v.z);
    __nv_bfloat16 h3 = __float2bfloat16(v.w);
    __nv_bfloat16 l0 = __float2bfloat16(v.x - __bfloat162float(h0));
    __nv_bfloat16 l1 = __float2bfloat16(v.y - __bfloat162float(h1));
    __nv_bfloat16 l2 = __float2bfloat16(v.z - __bfloat162float(h2));
    __nv_bfloat16 l3 = __float2bfloat16(v.w - __bfloat162float(h3));
    __nv_bfloat162 hp0 = __halves2bfloat162(h0, h1);
    __nv_bfloat162 hp1 = __halves2bfloat162(h2, h3);
    __nv_bfloat162 lp0 = __halves2bfloat162(l0, l1);
    __nv_bfloat162 lp1 = __halves2bfloat162(l2, l3);
    *(uint2*)hi = make_uint2(*(uint32_t*)&hp0, *(uint32_t*)&hp1);
    *(uint2*)lo = make_uint2(*(uint32_t*)&lp0, *(uint32_t*)&lp1);
}

// ================= tensor-core GEMM (mma.sync bf16, 3-term split) ============
// Y[N_NODES, N_OUT] = A[N_NODES, K] @ W[K, N_OUT] + bias
// Block: 128x128 tile, 8 warps (4m x 2n), warp tile 32x64, K chunk 32.
template <int N_OUT>
__global__ __launch_bounds__(256) void gemm_mma_kernel(
    const float* __restrict__ A, const float* __restrict__ W,
    const float* __restrict__ bias, float* __restrict__ Y, int K)
{
    __shared__ __align__(16) __nv_bfloat16 sA[2][128][40];   // hi/lo, pad 8
    __shared__ __align__(16) __nv_bfloat16 sB[2][32][136];   // hi/lo, pad 8

    const int t    = threadIdx.x;
    const int lane = t & 31;
    const int wid  = t >> 5;
    const int wm   = wid & 3;          // warp row group (32 rows)
    const int wn   = wid >> 2;         // warp col group (64 cols)
    const int r0   = blockIdx.x * 128;
    const int c0   = blockIdx.y * 128;

    float acc[2][8][4] = {};           // [m-atom][n-atom][frag]

    const int aRow = lane & 15;
    const int aCol = (lane >> 4) * 8;
    const int bK   = lane & 15;
    const int bN   = (lane >> 4) * 8;

    for (int kc = 0; kc < K; kc += 32) {
        // ---- stage A: 128 rows x 32 k (1024 float4, 4 per thread) ----------
#pragma unroll
        for (int it = 0; it < 4; ++it) {
            int fid = t + it * 256;
            int row = fid >> 3;
            int col = (fid & 7) * 4;
            int rg  = r0 + row;
            float4 a4 = make_float4(0.f, 0.f, 0.f, 0.f);
            if (rg < N_NODES) a4 = *(const float4*)&A[(size_t)rg * K + kc + col];
            cvt_split_store(&sA[0][row][col], &sA[1][row][col], a4);
        }
        // ---- stage B: 32 k x 128 n ------------------------------------------
#pragma unroll
        for (int it = 0; it < 4; ++it) {
            int fid = t + it * 256;
            int kk  = fid >> 5;
            int n   = (fid & 31) * 4;
            float4 w4 = *(const float4*)&W[(size_t)(kc + kk) * N_OUT + c0 + n];
            cvt_split_store(&sB[0][kk][n], &sB[1][kk][n], w4);
        }
        __syncthreads();

#pragma unroll
        for (int ks = 0; ks < 2; ++ks) {
            uint32_t aH[2][4], aL[2][4], bf[4][4];
#pragma unroll
            for (int mi = 0; mi < 2; ++mi) {
                ldsm_x4(aH[mi], smem_u32(&sA[0][wm * 32 + mi * 16 + aRow][ks * 16 + aCol]));
                ldsm_x4(aL[mi], smem_u32(&sA[1][wm * 32 + mi * 16 + aRow][ks * 16 + aCol]));
            }
            // B hi fragments (shared by Ah and Al passes)
#pragma unroll
            for (int pi = 0; pi < 4; ++pi)
                ldsm_x4_t(bf[pi], smem_u32(&sB[0][ks * 16 + bK][wn * 64 + pi * 16 + bN]));
#pragma unroll
            for (int mi = 0; mi < 2; ++mi)
#pragma unroll
                for (int pi = 0; pi < 4; ++pi) {
                    mma16816(acc[mi][2 * pi],     aH[mi], &bf[pi][0]);
                    mma16816(acc[mi][2 * pi + 1], aH[mi], &bf[pi][2]);
                }
#pragma unroll
            for (int mi = 0; mi < 2; ++mi)
#pragma unroll
                for (int pi = 0; pi < 4; ++pi) {
                    mma16816(acc[mi][2 * pi],     aL[mi], &bf[pi][0]);
                    mma16816(acc[mi][2 * pi + 1], aL[mi], &bf[pi][2]);
                }
            // B lo fragments with Ah
#pragma unroll
            for (int pi = 0; pi < 4; ++pi)
                ldsm_x4_t(bf[pi], smem_u32(&sB[1][ks * 16 + bK][wn * 64 + pi * 16 + bN]));
#pragma unroll
            for (int mi = 0; mi < 2; ++mi)
#pragma unroll
                for (int pi = 0; pi < 4; ++pi) {
                    mma16816(acc[mi][2 * pi],     aH[mi], &bf[pi][0]);
                    mma16816(acc[mi][2 * pi + 1], aH[mi], &bf[pi][2]);
                }
        }
        __syncthreads();
    }

    // ---- epilogue: bias + store ------------------------------------------------
#pragma unroll
    for (int mi = 0; mi < 2; ++mi) {
        int rA = r0 + wm * 32 + mi * 16 + (lane >> 2);
        int rB = rA + 8;
#pragma unroll
        for (int ni = 0; ni < 8; ++ni) {
            int col = c0 + wn * 64 + ni * 8 + (lane & 3) * 2;
            float2 bv = *(const float2*)&bias[col];
            if (rA < N_NODES) {
                float2 o = make_float2(acc[mi][ni][0] + bv.x, acc[mi][ni][1] + bv.y);
                *(float2*)&Y[(size_t)rA * N_OUT + col] = o;
            }
            if (rB < N_NODES) {
                float2 o = make_float2(acc[mi][ni][2] + bv.x, acc[mi][ni][3] + bv.y);
                *(float2*)&Y[(size_t)rB * N_OUT + col] = o;
            }
        }
    }
}

// =============== CSR build ====================================================
__global__ __launch_bounds__(256) void zero_wof_kernel() {
    int i = blockIdx.x * blockDim.x + threadIdx.x;
    if (i < N_NODES) g_wof[i] = 0;
}

__global__ __launch_bounds__(256) void hist_kernel(const int* __restrict__ ei) {
    int e = blockIdx.x * blockDim.x + threadIdx.x;
    if (e < N_EDGES) atomicAdd(&g_wof[ei[N_EDGES + e]], 1);
}

__global__ __launch_bounds__(1024) void scan_kernel() {
    __shared__ int sbuf[2][1024];
    int t = threadIdx.x;
    int carry = 0;
    for (int base = 0; base < N_NODES; base += 1024) {
        int i = base + t;
        int v = (i < N_NODES) ? g_wof[i] : 0;
        int pin = 0;
        sbuf[0][t] = v;
        __syncthreads();
#pragma unroll
        for (int off = 1; off < 1024; off <<= 1) {
            int x = sbuf[pin][t];
            if (t >= off) x += sbuf[pin][t - off];
            sbuf[pin ^ 1][t] = x;
            __syncthreads();
            pin ^= 1;
        }
        int incl = sbuf[pin][t];
        int tot  = sbuf[pin][1023];
        int excl = incl - v + carry;
        if (i < N_NODES) { g_rowptr[i] = excl; g_wof[i] = excl; }
        carry += tot;
        __syncthreads();
    }
    if (t == 0) g_rowptr[N_NODES] = carry;
}

__global__ __launch_bounds__(256) void csr_scatter_kernel(
    const int* __restrict__ ei, const float* __restrict__ ea)
{
    int e = blockIdx.x * blockDim.x + threadIdx.x;
    if (e >= N_EDGES) return;
    int src = ei[e];
    int dst = ei[N_EDGES + e];
    int pos = atomicAdd(&g_wof[dst], 1);
    g_csrc[pos] = src;
    g_cw[pos]   = ea[e];
}

// =============== per-node attention (warp per node, CSR) ======================
template <int CONCAT>
__global__ __launch_bounds__(256) void node_attn_kernel(
    const float* __restrict__ q, const float* __restrict__ k,
    const float* __restrict__ v, const float* __restrict__ skip,
    const float* __restrict__ We, float* __restrict__ out)
{
    int n = blockIdx.x * 8 + (threadIdx.x >> 5);
    if (n >= N_NODES) return;
    int lane = threadIdx.x & 31;
    int beg = g_rowptr[n], end = g_rowptr[n + 1];
    int off0 = lane * 4, off1 = 128 + lane * 4;

    const float* qr = q + (size_t)n * 256;
    float4 q0 = *(const float4*)(qr + off0);
    float4 q1 = *(const float4*)(qr + off1);
    float4 e0 = *(const float4*)(We + off0);
    float4 e1 = *(const float4*)(We + off1);

    const float scale = 0.08838834764831845f;

    float m0 = -INFINITY, m1 = -INFINITY;
    for (int p = beg; p < end; p++) {
        int s = g_csrc[p];
        float w = g_cw[p];
        const float* kr = k + (size_t)s * 256;
        float4 k0 = *(const float4*)(kr + off0);
        float4 k1 = *(const float4*)(kr + off1);
        float s0 = q0.x * fmaf(w, e0.x, k0.x) + q0.y * fmaf(w, e0.y, k0.y)
                 + q0.z * fmaf(w, e0.z, k0.z) + q0.w * fmaf(w, e0.w, k0.w);
        float s1 = q1.x * fmaf(w, e1.x, k1.x) + q1.y * fmaf(w, e1.y, k1.y)
                 + q1.z * fmaf(w, e1.z, k1.z) + q1.w * fmaf(w, e1.w, k1.w);
#pragma unroll
        for (int o = 16; o; o >>= 1) {
            s0 += __shfl_xor_sync(0xffffffffu, s0, o);
            s1 += __shfl_xor_sync(0xffffffffu, s1, o);
        }
        s0 *= scale; s1 *= scale;
        if (lane == 0) { g_alpha[2 * p] = s0; g_alpha[2 * p + 1] = s1; }
        m0 = fmaxf(m0, s0);
        m1 = fmaxf(m1, s1);
    }

    float d0 = 0.f, d1 = 0.f;
    float4 a0 = make_float4(0.f, 0.f, 0.f, 0.f);
    float4 a1 = make_float4(0.f, 0.f, 0.f, 0.f);
    for (int p = beg; p < end; p++) {
        int s = g_csrc[p];
        float w = g_cw[p];
        float x0 = expf(g_alpha[2 * p]     - m0);
        float x1 = expf(g_alpha[2 * p + 1] - m1);
        d0 += x0; d1 += x1;
        const float* vr = v + (size_t)s * 256;
        float4 v0 = *(const float4*)(vr + off0);
        float4 v1 = *(const float4*)(vr + off1);
        a0.x += x0 * fmaf(w, e0.x, v0.x);
        a0.y += x0 * fmaf(w, e0.y, v0.y);
        a0.z += x0 * fmaf(w, e0.z, v0.z);
        a0.w += x0 * fmaf(w, e0.w, v0.w);
        a1.x += x1 * fmaf(w, e1.x, v1.x);
        a1.y += x1 * fmaf(w, e1.y, v1.y);
        a1.z += x1 * fmaf(w, e1.z, v1.z);
        a1.w += x1 * fmaf(w, e1.w, v1.w);
    }
    float r0 = d0 > 0.f ? 1.f / d0 : 0.f;
    float r1 = d1 > 0.f ? 1.f / d1 : 0.f;
    a0.x *= r0; a0.y *= r0; a0.z *= r0; a0.w *= r0;
    a1.x *= r1; a1.y *= r1; a1.z *= r1; a1.w *= r1;

    if (CONCAT) {
        const float* sr = skip + (size_t)n * 256;
        float4 s0 = *(const float4*)(sr + off0);
        float4 s1 = *(const float4*)(sr + off1);
        float4 o0, o1;
        o0.x = fmaxf(a0.x + s0.x, 0.f); o0.y = fmaxf(a0.y + s0.y, 0.f);
        o0.z = fmaxf(a0.z + s0.z, 0.f); o0.w = fmaxf(a0.w + s0.w, 0.f);
        o1.x = fmaxf(a1.x + s1.x, 0.f); o1.y = fmaxf(a1.y + s1.y, 0.f);
        o1.z = fmaxf(a1.z + s1.z, 0.f); o1.w = fmaxf(a1.w + s1.w, 0.f);
        *(float4*)(out + (size_t)n * 256 + off0) = o0;
        *(float4*)(out + (size_t)n * 256 + off1) = o1;
    } else {
        float4 sk = *(const float4*)(skip + (size_t)n * 128 + off0);
        float4 o;
        o.x = 0.5f * (a0.x + a1.x) + sk.x;
        o.y = 0.5f * (a0.y + a1.y) + sk.y;
        o.z = 0.5f * (a0.z + a1.z) + sk.z;
        o.w = 0.5f * (a0.w + a1.w) + sk.w;
        *(float4*)(out + (size_t)n * 128 + off0) = o;
    }
}

// =============== pooling =======================================================
__global__ __launch_bounds__(256) void pool_zero_kernel(float* __restrict__ out) {
    int i = blockIdx.x * blockDim.x + threadIdx.x;
    if (i < N_GRAPHS * 128) out[i] = 0.f;
    if (i < N_GRAPHS) g_cnt[i] = 0.f;
}

__global__ __launch_bounds__(128) void pool_sum_kernel(
    const int* __restrict__ batch, const float* __restrict__ h,
    float* __restrict__ out)
{
    int n = blockIdx.x;
    int c = threadIdx.x;
    int g = batch[n];
    atomicAdd(&out[(size_t)g * 128 + c], h[(size_t)n * 128 + c]);
    if (c == 0) atomicAdd(&g_cnt[g], 1.f);
}

__global__ __launch_bounds__(256) void pool_div_kernel(float* __restrict__ out) {
    int i = blockIdx.x * blockDim.x + threadIdx.x;
    if (i >= N_GRAPHS * 128) return;
    out[i] /= fmaxf(g_cnt[i >> 7], 1.f);
}

// =============== launch =========================================================
extern "C" void kernel_launch(void* const* d_in, const int* in_sizes, int n_in,
                              void* d_out, int out_size)
{
    const float* x     = (const float*)d_in[0];
    const int*   ei    = (const int*)d_in[1];
    const int*   batch = (const int*)d_in[2];
    const float* ea    = (const float*)d_in[3];
    const float* Wq1 = (const float*)d_in[4];
    const float* bq1 = (const float*)d_in[5];
    const float* Wk1 = (const float*)d_in[6];
    const float* bk1 = (const float*)d_in[7];
    const float* Wv1 = (const float*)d_in[8];
    const float* bv1 = (const float*)d_in[9];
    const float* We1 = (const float*)d_in[10];
    const float* Ws1 = (const float*)d_in[11];
    const float* bs1 = (const float*)d_in[12];
    const float* Wq2 = (const float*)d_in[13];
    const float* bq2 = (const float*)d_in[14];
    const float* Wk2 = (const float*)d_in[15];
    const float* bk2 = (const float*)d_in[16];
    const float* Wv2 = (const float*)d_in[17];
    const float* bv2 = (const float*)d_in[18];
    const float* We2 = (const float*)d_in[19];
    const float* Ws2 = (const float*)d_in[20];
    const float* bs2 = (const float*)d_in[21];
    float* out = (float*)d_out;

    float *pq, *pk, *pv, *pskip, *ph;
    cudaGetSymbolAddress((void**)&pq,    g_q);
    cudaGetSymbolAddress((void**)&pk,    g_k);
    cudaGetSymbolAddress((void**)&pv,    g_v);
    cudaGetSymbolAddress((void**)&pskip, g_skip);
    cudaGetSymbolAddress((void**)&ph,    g_h);

    const int RT  = (N_NODES + 127) / 128;            // 391 row tiles
    dim3 gm2(RT, 2), gm1(RT, 1);

    const int EB  = (N_EDGES + 255) / 256;
    const int NB  = (N_NODES + 255) / 256;
    const int NWB = (N_NODES + 7) / 8;
    const int PZ  = (N_GRAPHS * 128 + 255) / 256;

    // ---- CSR build (shared by both layers) ----
    zero_wof_kernel<<<NB, 256>>>();
    hist_kernel<<<EB, 256>>>(ei);
    scan_kernel<<<1, 1024>>>();
    csr_scatter_kernel<<<EB, 256>>>(ei, ea);

    // ---- layer 1 (in=128, concat heads) ----
    gemm_mma_kernel<256><<<gm2, 256>>>(x, Wq1, bq1, pq, 128);
    gemm_mma_kernel<256><<<gm2, 256>>>(x, Wk1, bk1, pk, 128);
    gemm_mma_kernel<256><<<gm2, 256>>>(x, Wv1, bv1, pv, 128);
    gemm_mma_kernel<256><<<gm2, 256>>>(x, Ws1, bs1, pskip, 128);
    node_attn_kernel<1><<<NWB, 256>>>(pq, pk, pv, pskip, We1, ph);

    // ---- layer 2 (in=256, mean heads) ----
    gemm_mma_kernel<256><<<gm2, 256>>>(ph, Wq2, bq2, pq, 256);
    gemm_mma_kernel<256><<<gm2, 256>>>(ph, Wk2, bk2, pk, 256);
    gemm_mma_kernel<256><<<gm2, 256>>>(ph, Wv2, bv2, pv, 256);
    gemm_mma_kernel<128><<<gm1, 256>>>(ph, Ws2, bs2, pskip, 256);
    node_attn_kernel<0><<<NWB, 256>>>(pq, pk, pv, pskip, We2, ph);

    // ---- global mean pool ----
    pool_zero_kernel<<<PZ, 256>>>(out);
    pool_sum_kernel<<<N_NODES, 128>>>(batch, ph, out);
    pool_div_kernel<<<PZ, 256>>>(out);
}

// round 6
// speedup vs baseline: 3.7182x; 1.0976x over previous
#include <cuda_runtime.h>
#include <cuda_bf16.h>
#include <math.h>
#include <stdint.h>

#define N_NODES  50000
#define N_EDGES  800000
#define N_GRAPHS 2500

// ---------------- scratch (device globals; no allocations allowed) ----------
__device__ __align__(256) float g_q[N_NODES * 256];
__device__ __align__(256) float g_k[N_NODES * 256];
__device__ __align__(256) float g_v[N_NODES * 256];
__device__ __align__(256) float g_skip[N_NODES * 256];
__device__ __align__(256) float g_h[N_NODES * 256];
__device__ __align__(256) float g_cw[N_EDGES];
__device__ __align__(256) int   g_csrc[N_EDGES];
__device__ __align__(256) int   g_rowptr[N_NODES + 1];
__device__ __align__(256) int   g_wof[N_NODES];
__device__ __align__(256) float g_cnt[N_GRAPHS];
// bf16 hi/lo split operands
__device__ __align__(256) __nv_bfloat16 g_ahi[N_NODES * 256];
__device__ __align__(256) __nv_bfloat16 g_alo[N_NODES * 256];
__device__ __align__(256) __nv_bfloat16 g_whi[262144];
__device__ __align__(256) __nv_bfloat16 g_wlo[262144];

// ================= warp-MMA helpers (sm_80+ path, no 'a' features) ==========
__device__ __forceinline__ uint32_t smem_u32(const void* p) {
    uint32_t a;
    asm("{ .reg .u64 t; cvta.to.shared.u64 t, %1; cvt.u32.u64 %0, t; }"
        : "=r"(a) : "l"(p));
    return a;
}

__device__ __forceinline__ void ldsm_x4(uint32_t r[4], uint32_t addr) {
    asm volatile("ldmatrix.sync.aligned.m8n8.x4.shared.b16 {%0,%1,%2,%3}, [%4];"
        : "=r"(r[0]), "=r"(r[1]), "=r"(r[2]), "=r"(r[3]) : "r"(addr));
}
__device__ __forceinline__ void ldsm_x4_t(uint32_t r[4], uint32_t addr) {
    asm volatile("ldmatrix.sync.aligned.m8n8.x4.trans.shared.b16 {%0,%1,%2,%3}, [%4];"
        : "=r"(r[0]), "=r"(r[1]), "=r"(r[2]), "=r"(r[3]) : "r"(addr));
}

__device__ __forceinline__ void mma16816(float d[4], const uint32_t a[4],
                                         const uint32_t b[2]) {
    asm volatile(
        "mma.sync.aligned.m16n8k16.row.col.f32.bf16.bf16.f32 "
        "{%0,%1,%2,%3}, {%4,%5,%6,%7}, {%8,%9}, {%0,%1,%2,%3};"
        : "+f"(d[0]), "+f"(d[1]), "+f"(d[2]), "+f"(d[3])
        : "r"(a[0]), "r"(a[1]), "r"(a[2]), "r"(a[3]), "r"(b[0]), "r"(b[1]));
}

// =============== fp32 -> bf16 hi/lo split (standalone pass) ===================
__global__ __launch_bounds__(256) void cvt_split_kernel(
    const float* __restrict__ src, __nv_bfloat16* __restrict__ hi,
    __nv_bfloat16* __restrict__ lo, int n4)
{
    int i = blockIdx.x * blockDim.x + threadIdx.x;
    if (i >= n4) return;
    float4 v = ((const float4*)src)[i];
    __nv_bfloat16 h0 = __float2bfloat16(v.x);
    __nv_bfloat16 h1 = __float2bfloat16(v.y);
    __nv_bfloat16 h2 = __float2bfloat16(v.z);
    __nv_bfloat16 h3 = __float2bfloat16(v.w);
    __nv_bfloat16 l0 = __float2bfloat16(v.x - __bfloat162float(h0));
    __nv_bfloat16 l1 = __float2bfloat16(v.y - __bfloat162float(h1));
    __nv_bfloat16 l2 = __float2bfloat16(v.z - __bfloat162float(h2));
    __nv_bfloat16 l3 = __float2bfloat16(v.w - __bfloat162float(h3));
    __nv_bfloat162 hp0 = __halves2bfloat162(h0, h1);
    __nv_bfloat162 hp1 = __halves2bfloat162(h2, h3);
    __nv_bfloat162 lp0 = __halves2bfloat162(l0, l1);
    __nv_bfloat162 lp1 = __halves2bfloat162(l2, l3);
    *(uint2*)&hi[i * 4] = make_uint2(*(uint32_t*)&hp0, *(uint32_t*)&hp1);
    *(uint2*)&lo[i * 4] = make_uint2(*(uint32_t*)&lp0, *(uint32_t*)&lp1);
}

// ================= tensor-core GEMM (mma.sync bf16, 3-term split) ============
// Y[N_NODES, N_OUT] = A[N_NODES, K] @ W[K, N_OUT] + bias   (A, W pre-split bf16)
// Block: 128x128 tile, 8 warps (4m x 2n), warp tile 32x64, K chunk 32.
template <int N_OUT>
__global__ __launch_bounds__(256) void gemm_mma_kernel(
    const __nv_bfloat16* __restrict__ aHi, const __nv_bfloat16* __restrict__ aLo,
    const __nv_bfloat16* __restrict__ wHi, const __nv_bfloat16* __restrict__ wLo,
    const float* __restrict__ bias, float* __restrict__ Y, int K)
{
    __shared__ __align__(16) __nv_bfloat16 sA[2][128][40];   // hi/lo, pad 8
    __shared__ __align__(16) __nv_bfloat16 sB[2][32][136];   // hi/lo, pad 8

    const int t    = threadIdx.x;
    const int lane = t & 31;
    const int wid  = t >> 5;
    const int wm   = wid & 3;
    const int wn   = wid >> 2;
    const int r0   = blockIdx.x * 128;
    const int c0   = blockIdx.y * 128;

    float acc[2][8][4] = {};

    const int aRow = lane & 15;
    const int aCol = (lane >> 4) * 8;
    const int bK   = lane & 15;
    const int bN   = (lane >> 4) * 8;

    const uint4 z4 = make_uint4(0, 0, 0, 0);

    for (int kc = 0; kc < K; kc += 32) {
        // ---- stage A: 128 rows x 32 k bf16 (16B = 8 elems per load) --------
#pragma unroll
        for (int it = 0; it < 2; ++it) {
            int fid = t + it * 256;              // 0..511
            int row = fid >> 2;
            int col = (fid & 3) * 8;
            int rg  = r0 + row;
            size_t gidx = (size_t)rg * K + kc + col;
            uint4 hv = (rg < N_NODES) ? *(const uint4*)&aHi[gidx] : z4;
            uint4 lv = (rg < N_NODES) ? *(const uint4*)&aLo[gidx] : z4;
            *(uint4*)&sA[0][row][col] = hv;
            *(uint4*)&sA[1][row][col] = lv;
        }
        // ---- stage B: 32 k x 128 n ------------------------------------------
#pragma unroll
        for (int it = 0; it < 2; ++it) {
            int fid = t + it * 256;
            int kk  = fid >> 4;
            int n   = (fid & 15) * 8;
            size_t gidx = (size_t)(kc + kk) * N_OUT + c0 + n;
            *(uint4*)&sB[0][kk][n] = *(const uint4*)&wHi[gidx];
            *(uint4*)&sB[1][kk][n] = *(const uint4*)&wLo[gidx];
        }
        __syncthreads();

#pragma unroll
        for (int ks = 0; ks < 2; ++ks) {
            uint32_t aH[2][4], aL[2][4], bf[4][4];
#pragma unroll
            for (int mi = 0; mi < 2; ++mi) {
                ldsm_x4(aH[mi], smem_u32(&sA[0][wm * 32 + mi * 16 + aRow][ks * 16 + aCol]));
                ldsm_x4(aL[mi], smem_u32(&sA[1][wm * 32 + mi * 16 + aRow][ks * 16 + aCol]));
            }
#pragma unroll
            for (int pi = 0; pi < 4; ++pi)
                ldsm_x4_t(bf[pi], smem_u32(&sB[0][ks * 16 + bK][wn * 64 + pi * 16 + bN]));
#pragma unroll
            for (int mi = 0; mi < 2; ++mi)
#pragma unroll
                for (int pi = 0; pi < 4; ++pi) {
                    mma16816(acc[mi][2 * pi],     aH[mi], &bf[pi][0]);
                    mma16816(acc[mi][2 * pi + 1], aH[mi], &bf[pi][2]);
                }
#pragma unroll
            for (int mi = 0; mi < 2; ++mi)
#pragma unroll
                for (int pi = 0; pi < 4; ++pi) {
                    mma16816(acc[mi][2 * pi],     aL[mi], &bf[pi][0]);
                    mma16816(acc[mi][2 * pi + 1], aL[mi], &bf[pi][2]);
                }
#pragma unroll
            for (int pi = 0; pi < 4; ++pi)
                ldsm_x4_t(bf[pi], smem_u32(&sB[1][ks * 16 + bK][wn * 64 + pi * 16 + bN]));
#pragma unroll
            for (int mi = 0; mi < 2; ++mi)
#pragma unroll
                for (int pi = 0; pi < 4; ++pi) {
                    mma16816(acc[mi][2 * pi],     aH[mi], &bf[pi][0]);
                    mma16816(acc[mi][2 * pi + 1], aH[mi], &bf[pi][2]);
                }
        }
        __syncthreads();
    }

    // ---- epilogue: bias + store -----------------------------------------------
#pragma unroll
    for (int mi = 0; mi < 2; ++mi) {
        int rA = r0 + wm * 32 + mi * 16 + (lane >> 2);
        int rB = rA + 8;
#pragma unroll
        for (int ni = 0; ni < 8; ++ni) {
            int col = c0 + wn * 64 + ni * 8 + (lane & 3) * 2;
            float2 bv = *(const float2*)&bias[col];
            if (rA < N_NODES) {
                float2 o = make_float2(acc[mi][ni][0] + bv.x, acc[mi][ni][1] + bv.y);
                *(float2*)&Y[(size_t)rA * N_OUT + col] = o;
            }
            if (rB < N_NODES) {
                float2 o = make_float2(acc[mi][ni][2] + bv.x, acc[mi][ni][3] + bv.y);
                *(float2*)&Y[(size_t)rB * N_OUT + col] = o;
            }
        }
    }
}

// =============== CSR build ====================================================
__global__ __launch_bounds__(256) void zero_wof_kernel() {
    int i = blockIdx.x * blockDim.x + threadIdx.x;
    if (i < N_NODES) g_wof[i] = 0;
}

__global__ __launch_bounds__(256) void hist_kernel(const int* __restrict__ ei) {
    int e = blockIdx.x * blockDim.x + threadIdx.x;
    if (e < N_EDGES) atomicAdd(&g_wof[ei[N_EDGES + e]], 1);
}

__global__ __launch_bounds__(1024) void scan_kernel() {
    __shared__ int sbuf[2][1024];
    int t = threadIdx.x;
    int carry = 0;
    for (int base = 0; base < N_NODES; base += 1024) {
        int i = base + t;
        int v = (i < N_NODES) ? g_wof[i] : 0;
        int pin = 0;
        sbuf[0][t] = v;
        __syncthreads();
#pragma unroll
        for (int off = 1; off < 1024; off <<= 1) {
            int x = sbuf[pin][t];
            if (t >= off) x += sbuf[pin][t - off];
            sbuf[pin ^ 1][t] = x;
            __syncthreads();
            pin ^= 1;
        }
        int incl = sbuf[pin][t];
        int tot  = sbuf[pin][1023];
        int excl = incl - v + carry;
        if (i < N_NODES) { g_rowptr[i] = excl; g_wof[i] = excl; }
        carry += tot;
        __syncthreads();
    }
    if (t == 0) g_rowptr[N_NODES] = carry;
}

__global__ __launch_bounds__(256) void csr_scatter_kernel(
    const int* __restrict__ ei, const float* __restrict__ ea)
{
    int e = blockIdx.x * blockDim.x + threadIdx.x;
    if (e >= N_EDGES) return;
    int src = ei[e];
    int dst = ei[N_EDGES + e];
    int pos = atomicAdd(&g_wof[dst], 1);
    g_csrc[pos] = src;
    g_cw[pos]   = ea[e];
}

// =============== per-node attention: SINGLE PASS (no max; shift-invariant) ===
template <int CONCAT>
__global__ __launch_bounds__(256) void node_attn_kernel(
    const float* __restrict__ q, const float* __restrict__ k,
    const float* __restrict__ v, const float* __restrict__ skip,
    const float* __restrict__ We, float* __restrict__ out)
{
    int n = blockIdx.x * 8 + (threadIdx.x >> 5);
    if (n >= N_NODES) return;
    int lane = threadIdx.x & 31;
    int beg = g_rowptr[n], end = g_rowptr[n + 1];
    int off0 = lane * 4, off1 = 128 + lane * 4;

    const float* qr = q + (size_t)n * 256;
    float4 q0 = *(const float4*)(qr + off0);
    float4 q1 = *(const float4*)(qr + off1);
    float4 e0 = *(const float4*)(We + off0);
    float4 e1 = *(const float4*)(We + off1);

    const float scale = 0.08838834764831845f;   // 1/sqrt(128)

    float d0 = 0.f, d1 = 0.f;
    float4 a0 = make_float4(0.f, 0.f, 0.f, 0.f);
    float4 a1 = make_float4(0.f, 0.f, 0.f, 0.f);

    int p = beg;
    // ---- unrolled by 2: 4 shuffle-reduce chains interleaved ----
    for (; p + 1 < end; p += 2) {
        int  sa = g_csrc[p],  sb = g_csrc[p + 1];
        float wa = g_cw[p],   wb = g_cw[p + 1];
        const float* krA = k + (size_t)sa * 256;
        const float* vrA = v + (size_t)sa * 256;
        const float* krB = k + (size_t)sb * 256;
        const float* vrB = v + (size_t)sb * 256;
        float4 kA0 = *(const float4*)(krA + off0);
        float4 kA1 = *(const float4*)(krA + off1);
        float4 kB0 = *(const float4*)(krB + off0);
        float4 kB1 = *(const float4*)(krB + off1);
        float4 vA0 = *(const float4*)(vrA + off0);
        float4 vA1 = *(const float4*)(vrA + off1);
        float4 vB0 = *(const float4*)(vrB + off0);
        float4 vB1 = *(const float4*)(vrB + off1);

        float sA0 = q0.x * fmaf(wa, e0.x, kA0.x) + q0.y * fmaf(wa, e0.y, kA0.y)
                  + q0.z * fmaf(wa, e0.z, kA0.z) + q0.w * fmaf(wa, e0.w, kA0.w);
        float sA1 = q1.x * fmaf(wa, e1.x, kA1.x) + q1.y * fmaf(wa, e1.y, kA1.y)
                  + q1.z * fmaf(wa, e1.z, kA1.z) + q1.w * fmaf(wa, e1.w, kA1.w);
        float sB0 = q0.x * fmaf(wb, e0.x, kB0.x) + q0.y * fmaf(wb, e0.y, kB0.y)
                  + q0.z * fmaf(wb, e0.z, kB0.z) + q0.w * fmaf(wb, e0.w, kB0.w);
        float sB1 = q1.x * fmaf(wb, e1.x, kB1.x) + q1.y * fmaf(wb, e1.y, kB1.y)
                  + q1.z * fmaf(wb, e1.z, kB1.z) + q1.w * fmaf(wb, e1.w, kB1.w);
#pragma unroll
        for (int o = 16; o; o >>= 1) {
            sA0 += __shfl_xor_sync(0xffffffffu, sA0, o);
            sA1 += __shfl_xor_sync(0xffffffffu, sA1, o);
            sB0 += __shfl_xor_sync(0xffffffffu, sB0, o);
            sB1 += __shfl_xor_sync(0xffffffffu, sB1, o);
        }
        float xA0 = __expf(sA0 * scale), xA1 = __expf(sA1 * scale);
        float xB0 = __expf(sB0 * scale), xB1 = __expf(sB1 * scale);
        d0 += xA0 + xB0;
        d1 += xA1 + xB1;
        a0.x += xA0 * fmaf(wa, e0.x, vA0.x) + xB0 * fmaf(wb, e0.x, vB0.x);
        a0.y += xA0 * fmaf(wa, e0.y, vA0.y) + xB0 * fmaf(wb, e0.y, vB0.y);
        a0.z += xA0 * fmaf(wa, e0.z, vA0.z) + xB0 * fmaf(wb, e0.z, vB0.z);
        a0.w += xA0 * fmaf(wa, e0.w, vA0.w) + xB0 * fmaf(wb, e0.w, vB0.w);
        a1.x += xA1 * fmaf(wa, e1.x, vA1.x) + xB1 * fmaf(wb, e1.x, vB1.x);
        a1.y += xA1 * fmaf(wa, e1.y, vA1.y) + xB1 * fmaf(wb, e1.y, vB1.y);
        a1.z += xA1 * fmaf(wa, e1.z, vA1.z) + xB1 * fmaf(wb, e1.z, vB1.z);
        a1.w += xA1 * fmaf(wa, e1.w, vA1.w) + xB1 * fmaf(wb, e1.w, vB1.w);
    }
    // ---- tail ----
    for (; p < end; ++p) {
        int s = g_csrc[p];
        float w = g_cw[p];
        const float* kr = k + (size_t)s * 256;
        const float* vr = v + (size_t)s * 256;
        float4 k0 = *(const float4*)(kr + off0);
        float4 k1 = *(const float4*)(kr + off1);
        float4 v0 = *(const float4*)(vr + off0);
        float4 v1 = *(const float4*)(vr + off1);
        float s0 = q0.x * fmaf(w, e0.x, k0.x) + q0.y * fmaf(w, e0.y, k0.y)
                 + q0.z * fmaf(w, e0.z, k0.z) + q0.w * fmaf(w, e0.w, k0.w);
        float s1 = q1.x * fmaf(w, e1.x, k1.x) + q1.y * fmaf(w, e1.y, k1.y)
                 + q1.z * fmaf(w, e1.z, k1.z) + q1.w * fmaf(w, e1.w, k1.w);
#pragma unroll
        for (int o = 16; o; o >>= 1) {
            s0 += __shfl_xor_sync(0xffffffffu, s0, o);
            s1 += __shfl_xor_sync(0xffffffffu, s1, o);
        }
        float x0 = __expf(s0 * scale), x1 = __expf(s1 * scale);
        d0 += x0; d1 += x1;
        a0.x += x0 * fmaf(w, e0.x, v0.x);
        a0.y += x0 * fmaf(w, e0.y, v0.y);
        a0.z += x0 * fmaf(w, e0.z, v0.z);
        a0.w += x0 * fmaf(w, e0.w, v0.w);
        a1.x += x1 * fmaf(w, e1.x, v1.x);
        a1.y += x1 * fmaf(w, e1.y, v1.y);
        a1.z += x1 * fmaf(w, e1.z, v1.z);
        a1.w += x1 * fmaf(w, e1.w, v1.w);
    }

    float r0 = d0 > 0.f ? 1.f / d0 : 0.f;
    float r1 = d1 > 0.f ? 1.f / d1 : 0.f;
    a0.x *= r0; a0.y *= r0; a0.z *= r0; a0.w *= r0;
    a1.x *= r1; a1.y *= r1; a1.z *= r1; a1.w *= r1;

    if (CONCAT) {
        const float* sr = skip + (size_t)n * 256;
        float4 s0 = *(const float4*)(sr + off0);
        float4 s1 = *(const float4*)(sr + off1);
        float4 o0, o1;
        o0.x = fmaxf(a0.x + s0.x, 0.f); o0.y = fmaxf(a0.y + s0.y, 0.f);
        o0.z = fmaxf(a0.z + s0.z, 0.f); o0.w = fmaxf(a0.w + s0.w, 0.f);
        o1.x = fmaxf(a1.x + s1.x, 0.f); o1.y = fmaxf(a1.y + s1.y, 0.f);
        o1.z = fmaxf(a1.z + s1.z, 0.f); o1.w = fmaxf(a1.w + s1.w, 0.f);
        *(float4*)(out + (size_t)n * 256 + off0) = o0;
        *(float4*)(out + (size_t)n * 256 + off1) = o1;
    } else {
        float4 sk = *(const float4*)(skip + (size_t)n * 128 + off0);
        float4 o;
        o.x = 0.5f * (a0.x + a1.x) + sk.x;
        o.y = 0.5f * (a0.y + a1.y) + sk.y;
        o.z = 0.5f * (a0.z + a1.z) + sk.z;
        o.w = 0.5f * (a0.w + a1.w) + sk.w;
        *(float4*)(out + (size_t)n * 128 + off0) = o;
    }
}

// =============== pooling =======================================================
__global__ __launch_bounds__(256) void pool_zero_kernel(float* __restrict__ out) {
    int i = blockIdx.x * blockDim.x + threadIdx.x;
    if (i < N_GRAPHS * 128) out[i] = 0.f;
    if (i < N_GRAPHS) g_cnt[i] = 0.f;
}

__global__ __launch_bounds__(128) void pool_sum_kernel(
    const int* __restrict__ batch, const float* __restrict__ h,
    float* __restrict__ out)
{
    int n = blockIdx.x;
    int c = threadIdx.x;
    int g = batch[n];
    atomicAdd(&out[(size_t)g * 128 + c], h[(size_t)n * 128 + c]);
    if (c == 0) atomicAdd(&g_cnt[g], 1.f);
}

__global__ __launch_bounds__(256) void pool_div_kernel(float* __restrict__ out) {
    int i = blockIdx.x * blockDim.x + threadIdx.x;
    if (i >= N_GRAPHS * 128) return;
    out[i] /= fmaxf(g_cnt[i >> 7], 1.f);
}

// =============== launch =========================================================
extern "C" void kernel_launch(void* const* d_in, const int* in_sizes, int n_in,
                              void* d_out, int out_size)
{
    const float* x     = (const float*)d_in[0];
    const int*   ei    = (const int*)d_in[1];
    const int*   batch = (const int*)d_in[2];
    const float* ea    = (const float*)d_in[3];
    const float* Wq1 = (const float*)d_in[4];
    const float* bq1 = (const float*)d_in[5];
    const float* Wk1 = (const float*)d_in[6];
    const float* bk1 = (const float*)d_in[7];
    const float* Wv1 = (const float*)d_in[8];
    const float* bv1 = (const float*)d_in[9];
    const float* We1 = (const float*)d_in[10];
    const float* Ws1 = (const float*)d_in[11];
    const float* bs1 = (const float*)d_in[12];
    const float* Wq2 = (const float*)d_in[13];
    const float* bq2 = (const float*)d_in[14];
    const float* Wk2 = (const float*)d_in[15];
    const float* bk2 = (const float*)d_in[16];
    const float* Wv2 = (const float*)d_in[17];
    const float* bv2 = (const float*)d_in[18];
    const float* We2 = (const float*)d_in[19];
    const float* Ws2 = (const float*)d_in[20];
    const float* bs2 = (const float*)d_in[21];
    float* out = (float*)d_out;

    float *pq, *pk, *pv, *pskip, *ph;
    __nv_bfloat16 *pahi, *palo, *pwhi, *pwlo;
    cudaGetSymbolAddress((void**)&pq,    g_q);
    cudaGetSymbolAddress((void**)&pk,    g_k);
    cudaGetSymbolAddress((void**)&pv,    g_v);
    cudaGetSymbolAddress((void**)&pskip, g_skip);
    cudaGetSymbolAddress((void**)&ph,    g_h);
    cudaGetSymbolAddress((void**)&pahi,  g_ahi);
    cudaGetSymbolAddress((void**)&palo,  g_alo);
    cudaGetSymbolAddress((void**)&pwhi,  g_whi);
    cudaGetSymbolAddress((void**)&pwlo,  g_wlo);

    const int RT  = (N_NODES + 127) / 128;            // 391 row tiles
    dim3 gm2(RT, 2), gm1(RT, 1);

    const int EB  = (N_EDGES + 255) / 256;
    const int NB  = (N_NODES + 255) / 256;
    const int NWB = (N_NODES + 7) / 8;
    const int PZ  = (N_GRAPHS * 128 + 255) / 256;

    auto cvt = [&](const float* src, __nv_bfloat16* hi, __nv_bfloat16* lo, int cnt) {
        int n4 = cnt / 4;
        cvt_split_kernel<<<(n4 + 255) / 256, 256>>>(src, hi, lo, n4);
    };

    // ---- CSR build (shared by both layers) ----
    zero_wof_kernel<<<NB, 256>>>();
    hist_kernel<<<EB, 256>>>(ei);
    scan_kernel<<<1, 1024>>>();
    csr_scatter_kernel<<<EB, 256>>>(ei, ea);

    // ---- layer 1 (in=128, concat heads) ----
    cvt(x, pahi, palo, N_NODES * 128);
    cvt(Wq1, pwhi,          pwlo,          128 * 256);
    cvt(Wk1, pwhi + 65536,  pwlo + 65536,  128 * 256);
    cvt(Wv1, pwhi + 131072, pwlo + 131072, 128 * 256);
    cvt(Ws1, pwhi + 196608, pwlo + 196608, 128 * 256);
    gemm_mma_kernel<256><<<gm2, 256>>>(pahi, palo, pwhi,          pwlo,          bq1, pq,    128);
    gemm_mma_kernel<256><<<gm2, 256>>>(pahi, palo, pwhi + 65536,  pwlo + 65536,  bk1, pk,    128);
    gemm_mma_kernel<256><<<gm2, 256>>>(pahi, palo, pwhi + 131072, pwlo + 131072, bv1, pv,    128);
    gemm_mma_kernel<256><<<gm2, 256>>>(pahi, palo, pwhi + 196608, pwlo + 196608, bs1, pskip, 128);
    node_attn_kernel<1><<<NWB, 256>>>(pq, pk, pv, pskip, We1, ph);

    // ---- layer 2 (in=256, mean heads) ----
    cvt(ph, pahi, palo, N_NODES * 256);
    cvt(Wq2, pwhi,          pwlo,          256 * 256);
    cvt(Wk2, pwhi + 65536,  pwlo + 65536,  256 * 256);
    cvt(Wv2, pwhi + 131072, pwlo + 131072, 256 * 256);
    cvt(Ws2, pwhi + 196608, pwlo + 196608, 256 * 128);
    gemm_mma_kernel<256><<<gm2, 256>>>(pahi, palo, pwhi,          pwlo,          bq2, pq,    256);
    gemm_mma_kernel<256><<<gm2, 256>>>(pahi, palo, pwhi + 65536,  pwlo + 65536,  bk2, pk,    256);
    gemm_mma_kernel<256><<<gm2, 256>>>(pahi, palo, pwhi + 131072, pwlo + 131072, bv2, pv,    256);
    gemm_mma_kernel<128><<<gm1, 256>>>(pahi, palo, pwhi + 196608, pwlo + 196608, bs2, pskip, 256);
    node_attn_kernel<0><<<NWB, 256>>>(pq, pk, pv, pskip, We2, ph);

    // ---- global mean pool ----
    pool_zero_kernel<<<PZ, 256>>>(out);
    pool_sum_kernel<<<N_NODES, 128>>>(batch, ph, out);
    pool_div_kernel<<<PZ, 256>>>(out);
}

// round 7
// speedup vs baseline: 5.0234x; 1.3510x over previous
#include <cuda_runtime.h>
#include <cuda_bf16.h>
#include <math.h>
#include <stdint.h>

#define N_NODES  50000
#define N_EDGES  800000
#define N_GRAPHS 2500

// ---------------- scratch (device globals; no allocations allowed) ----------
__device__ __align__(256) float g_q[N_NODES * 256];
__device__ __align__(256) float g_skip[N_NODES * 256];
__device__ __align__(256) float g_h[N_NODES * 128];
__device__ __align__(256) float g_cw[N_EDGES];
__device__ __align__(256) int   g_csrc[N_EDGES];
__device__ __align__(256) int   g_rowptr[N_NODES + 1];
__device__ __align__(256) int   g_wof[N_NODES];
__device__ __align__(256) float g_cnt[N_GRAPHS];
// bf16 operands
__device__ __align__(256) __nv_bfloat16 g_kv[N_NODES * 512];   // [k(256) | v(256)]
__device__ __align__(256) __nv_bfloat16 g_ahi[N_NODES * 256];
__device__ __align__(256) __nv_bfloat16 g_alo[N_NODES * 256];
__device__ __align__(256) __nv_bfloat16 g_whi[262144];
__device__ __align__(256) __nv_bfloat16 g_wlo[262144];

// ================= warp-MMA helpers ==========================================
__device__ __forceinline__ uint32_t smem_u32(const void* p) {
    uint32_t a;
    asm("{ .reg .u64 t; cvta.to.shared.u64 t, %1; cvt.u32.u64 %0, t; }"
        : "=r"(a) : "l"(p));
    return a;
}

__device__ __forceinline__ void ldsm_x4(uint32_t r[4], uint32_t addr) {
    asm volatile("ldmatrix.sync.aligned.m8n8.x4.shared.b16 {%0,%1,%2,%3}, [%4];"
        : "=r"(r[0]), "=r"(r[1]), "=r"(r[2]), "=r"(r[3]) : "r"(addr));
}
__device__ __forceinline__ void ldsm_x4_t(uint32_t r[4], uint32_t addr) {
    asm volatile("ldmatrix.sync.aligned.m8n8.x4.trans.shared.b16 {%0,%1,%2,%3}, [%4];"
        : "=r"(r[0]), "=r"(r[1]), "=r"(r[2]), "=r"(r[3]) : "r"(addr));
}

__device__ __forceinline__ void mma16816(float d[4], const uint32_t a[4],
                                         const uint32_t b[2]) {
    asm volatile(
        "mma.sync.aligned.m16n8k16.row.col.f32.bf16.bf16.f32 "
        "{%0,%1,%2,%3}, {%4,%5,%6,%7}, {%8,%9}, {%0,%1,%2,%3};"
        : "+f"(d[0]), "+f"(d[1]), "+f"(d[2]), "+f"(d[3])
        : "r"(a[0]), "r"(a[1]), "r"(a[2]), "r"(a[3]), "r"(b[0]), "r"(b[1]));
}

__device__ __forceinline__ void bf8_to_f(const uint4& u, float* f) {
    float2 p;
    p = __bfloat1622float2(*(const __nv_bfloat162*)&u.x); f[0] = p.x; f[1] = p.y;
    p = __bfloat1622float2(*(const __nv_bfloat162*)&u.y); f[2] = p.x; f[3] = p.y;
    p = __bfloat1622float2(*(const __nv_bfloat162*)&u.z); f[4] = p.x; f[5] = p.y;
    p = __bfloat1622float2(*(const __nv_bfloat162*)&u.w); f[6] = p.x; f[7] = p.y;
}

// =============== fp32 -> bf16 hi/lo split (standalone pass) ===================
__global__ __launch_bounds__(256) void cvt_split_kernel(
    const float* __restrict__ src, __nv_bfloat16* __restrict__ hi,
    __nv_bfloat16* __restrict__ lo, int n4)
{
    int i = blockIdx.x * blockDim.x + threadIdx.x;
    if (i >= n4) return;
    float4 v = ((const float4*)src)[i];
    __nv_bfloat16 h0 = __float2bfloat16(v.x);
    __nv_bfloat16 h1 = __float2bfloat16(v.y);
    __nv_bfloat16 h2 = __float2bfloat16(v.z);
    __nv_bfloat16 h3 = __float2bfloat16(v.w);
    __nv_bfloat16 l0 = __float2bfloat16(v.x - __bfloat162float(h0));
    __nv_bfloat16 l1 = __float2bfloat16(v.y - __bfloat162float(h1));
    __nv_bfloat16 l2 = __float2bfloat16(v.z - __bfloat162float(h2));
    __nv_bfloat16 l3 = __float2bfloat16(v.w - __bfloat162float(h3));
    __nv_bfloat162 hp0 = __halves2bfloat162(h0, h1);
    __nv_bfloat162 hp1 = __halves2bfloat162(h2, h3);
    __nv_bfloat162 lp0 = __halves2bfloat162(l0, l1);
    __nv_bfloat162 lp1 = __halves2bfloat162(l2, l3);
    *(uint2*)&hi[i * 4] = make_uint2(*(uint32_t*)&hp0, *(uint32_t*)&hp1);
    *(uint2*)&lo[i * 4] = make_uint2(*(uint32_t*)&lp0, *(uint32_t*)&lp1);
}

// ================= tensor-core GEMM (mma.sync bf16, 3-term split) ============
// BF16OUT=0: fp32 out Yf (ld=ldY, col offset colOff); BF16OUT=1: bf16 out Yb.
template <int N_OUT, int BF16OUT>
__global__ __launch_bounds__(256) void gemm_mma_kernel(
    const __nv_bfloat16* __restrict__ aHi, const __nv_bfloat16* __restrict__ aLo,
    const __nv_bfloat16* __restrict__ wHi, const __nv_bfloat16* __restrict__ wLo,
    const float* __restrict__ bias, float* __restrict__ Yf,
    __nv_bfloat16* __restrict__ Yb, int ldY, int colOff, int K)
{
    __shared__ __align__(16) __nv_bfloat16 sA[2][128][40];
    __shared__ __align__(16) __nv_bfloat16 sB[2][32][136];

    const int t    = threadIdx.x;
    const int lane = t & 31;
    const int wid  = t >> 5;
    const int wm   = wid & 3;
    const int wn   = wid >> 2;
    const int r0   = blockIdx.x * 128;
    const int c0   = blockIdx.y * 128;

    float acc[2][8][4] = {};

    const int aRow = lane & 15;
    const int aCol = (lane >> 4) * 8;
    const int bK   = lane & 15;
    const int bN   = (lane >> 4) * 8;

    const uint4 z4 = make_uint4(0, 0, 0, 0);

    for (int kc = 0; kc < K; kc += 32) {
#pragma unroll
        for (int it = 0; it < 2; ++it) {
            int fid = t + it * 256;
            int row = fid >> 2;
            int col = (fid & 3) * 8;
            int rg  = r0 + row;
            size_t gidx = (size_t)rg * K + kc + col;
            uint4 hv = (rg < N_NODES) ? *(const uint4*)&aHi[gidx] : z4;
            uint4 lv = (rg < N_NODES) ? *(const uint4*)&aLo[gidx] : z4;
            *(uint4*)&sA[0][row][col] = hv;
            *(uint4*)&sA[1][row][col] = lv;
        }
#pragma unroll
        for (int it = 0; it < 2; ++it) {
            int fid = t + it * 256;
            int kk  = fid >> 4;
            int n   = (fid & 15) * 8;
            size_t gidx = (size_t)(kc + kk) * N_OUT + c0 + n;
            *(uint4*)&sB[0][kk][n] = *(const uint4*)&wHi[gidx];
            *(uint4*)&sB[1][kk][n] = *(const uint4*)&wLo[gidx];
        }
        __syncthreads();

#pragma unroll
        for (int ks = 0; ks < 2; ++ks) {
            uint32_t aH[2][4], aL[2][4], bf[4][4];
#pragma unroll
            for (int mi = 0; mi < 2; ++mi) {
                ldsm_x4(aH[mi], smem_u32(&sA[0][wm * 32 + mi * 16 + aRow][ks * 16 + aCol]));
                ldsm_x4(aL[mi], smem_u32(&sA[1][wm * 32 + mi * 16 + aRow][ks * 16 + aCol]));
            }
#pragma unroll
            for (int pi = 0; pi < 4; ++pi)
                ldsm_x4_t(bf[pi], smem_u32(&sB[0][ks * 16 + bK][wn * 64 + pi * 16 + bN]));
#pragma unroll
            for (int mi = 0; mi < 2; ++mi)
#pragma unroll
                for (int pi = 0; pi < 4; ++pi) {
                    mma16816(acc[mi][2 * pi],     aH[mi], &bf[pi][0]);
                    mma16816(acc[mi][2 * pi + 1], aH[mi], &bf[pi][2]);
                }
#pragma unroll
            for (int mi = 0; mi < 2; ++mi)
#pragma unroll
                for (int pi = 0; pi < 4; ++pi) {
                    mma16816(acc[mi][2 * pi],     aL[mi], &bf[pi][0]);
                    mma16816(acc[mi][2 * pi + 1], aL[mi], &bf[pi][2]);
                }
#pragma unroll
            for (int pi = 0; pi < 4; ++pi)
                ldsm_x4_t(bf[pi], smem_u32(&sB[1][ks * 16 + bK][wn * 64 + pi * 16 + bN]));
#pragma unroll
            for (int mi = 0; mi < 2; ++mi)
#pragma unroll
                for (int pi = 0; pi < 4; ++pi) {
                    mma16816(acc[mi][2 * pi],     aH[mi], &bf[pi][0]);
                    mma16816(acc[mi][2 * pi + 1], aH[mi], &bf[pi][2]);
                }
        }
        __syncthreads();
    }

#pragma unroll
    for (int mi = 0; mi < 2; ++mi) {
        int rA = r0 + wm * 32 + mi * 16 + (lane >> 2);
        int rB = rA + 8;
#pragma unroll
        for (int ni = 0; ni < 8; ++ni) {
            int cc  = c0 + wn * 64 + ni * 8 + (lane & 3) * 2;
            float2 bv = *(const float2*)&bias[cc];
            float x0 = acc[mi][ni][0] + bv.x, y0 = acc[mi][ni][1] + bv.y;
            float x1 = acc[mi][ni][2] + bv.x, y1 = acc[mi][ni][3] + bv.y;
            int col = colOff + cc;
            if (BF16OUT) {
                if (rA < N_NODES)
                    *(__nv_bfloat162*)&Yb[(size_t)rA * ldY + col] =
                        __floats2bfloat162_rn(x0, y0);
                if (rB < N_NODES)
                    *(__nv_bfloat162*)&Yb[(size_t)rB * ldY + col] =
                        __floats2bfloat162_rn(x1, y1);
            } else {
                if (rA < N_NODES)
                    *(float2*)&Yf[(size_t)rA * ldY + col] = make_float2(x0, y0);
                if (rB < N_NODES)
                    *(float2*)&Yf[(size_t)rB * ldY + col] = make_float2(x1, y1);
            }
        }
    }
}

// =============== CSR build ====================================================
__global__ __launch_bounds__(256) void zero_wof_kernel() {
    int i = blockIdx.x * blockDim.x + threadIdx.x;
    if (i < N_NODES) g_wof[i] = 0;
}

__global__ __launch_bounds__(256) void hist_kernel(const int* __restrict__ ei) {
    int e = blockIdx.x * blockDim.x + threadIdx.x;
    if (e < N_EDGES) atomicAdd(&g_wof[ei[N_EDGES + e]], 1);
}

__global__ __launch_bounds__(1024) void scan_kernel() {
    __shared__ int sbuf[2][1024];
    int t = threadIdx.x;
    int carry = 0;
    for (int base = 0; base < N_NODES; base += 1024) {
        int i = base + t;
        int v = (i < N_NODES) ? g_wof[i] : 0;
        int pin = 0;
        sbuf[0][t] = v;
        __syncthreads();
#pragma unroll
        for (int off = 1; off < 1024; off <<= 1) {
            int x = sbuf[pin][t];
            if (t >= off) x += sbuf[pin][t - off];
            sbuf[pin ^ 1][t] = x;
            __syncthreads();
            pin ^= 1;
        }
        int incl = sbuf[pin][t];
        int tot  = sbuf[pin][1023];
        int excl = incl - v + carry;
        if (i < N_NODES) { g_rowptr[i] = excl; g_wof[i] = excl; }
        carry += tot;
        __syncthreads();
    }
    if (t == 0) g_rowptr[N_NODES] = carry;
}

__global__ __launch_bounds__(256) void csr_scatter_kernel(
    const int* __restrict__ ei, const float* __restrict__ ea)
{
    int e = blockIdx.x * blockDim.x + threadIdx.x;
    if (e >= N_EDGES) return;
    int src = ei[e];
    int dst = ei[N_EDGES + e];
    int pos = atomicAdd(&g_wof[dst], 1);
    g_csrc[pos] = src;
    g_cw[pos]   = ea[e];
}

// =============== per-node attention: bf16 kv gather, half-warp heads ========
// Lane owns 8 channels: global channel = lane*8+i; head = lane>>4.
// CONCAT=1: writes hi/lo bf16 split of relu(attn+skip) [N,256]
// CONCAT=0: writes fp32 mean-head + skip [N,128]
template <int CONCAT>
__global__ __launch_bounds__(256, 2) void node_attn_kernel(
    const float* __restrict__ q, const __nv_bfloat16* __restrict__ kv,
    const float* __restrict__ skip, const float* __restrict__ We,
    float* __restrict__ outf, __nv_bfloat16* __restrict__ ohi,
    __nv_bfloat16* __restrict__ olo)
{
    int n = blockIdx.x * 8 + (threadIdx.x >> 5);
    if (n >= N_NODES) return;
    int lane = threadIdx.x & 31;
    int beg = g_rowptr[n], end = g_rowptr[n + 1];

    const float scale = 0.08838834764831845f;   // 1/sqrt(128)

    float qv[8], ev[8];
    {
        const float* qr = q + (size_t)n * 256 + lane * 8;
        *(float4*)&qv[0] = *(const float4*)(qr);
        *(float4*)&qv[4] = *(const float4*)(qr + 4);
        *(float4*)&ev[0] = *(const float4*)(We + lane * 8);
        *(float4*)&ev[4] = *(const float4*)(We + lane * 8 + 4);
    }
    // qe = scale * (q . We) for own head (16-lane reduce)
    float qe = 0.f;
#pragma unroll
    for (int i = 0; i < 8; ++i) qe = fmaf(qv[i], ev[i], qe);
#pragma unroll
    for (int o = 8; o; o >>= 1) qe += __shfl_xor_sync(0xffffffffu, qe, o);
    qe *= scale;

    float d = 0.f, cw = 0.f;
    float a[8] = {};

    int p = beg;
    for (; p + 1 < end; p += 2) {
        int  sa = g_csrc[p],  sb = g_csrc[p + 1];
        float wa = g_cw[p],   wb = g_cw[p + 1];
        const uint4* ra = (const uint4*)(kv + (size_t)sa * 512);
        const uint4* rb = (const uint4*)(kv + (size_t)sb * 512);
        uint4 kua = ra[lane], kub = rb[lane];
        uint4 vua = ra[32 + lane], vub = rb[32 + lane];

        float kfa[8], kfb[8];
        bf8_to_f(kua, kfa);
        bf8_to_f(kub, kfb);
        float ta = 0.f, tb = 0.f;
#pragma unroll
        for (int i = 0; i < 8; ++i) {
            ta = fmaf(qv[i], kfa[i], ta);
            tb = fmaf(qv[i], kfb[i], tb);
        }
#pragma unroll
        for (int o = 8; o; o >>= 1) {
            ta += __shfl_xor_sync(0xffffffffu, ta, o);
            tb += __shfl_xor_sync(0xffffffffu, tb, o);
        }
        float xa = __expf(fmaf(wa, qe, ta * scale));
        float xb = __expf(fmaf(wb, qe, tb * scale));
        d  += xa + xb;
        cw += xa * wa + xb * wb;
        float vfa[8], vfb[8];
        bf8_to_f(vua, vfa);
        bf8_to_f(vub, vfb);
#pragma unroll
        for (int i = 0; i < 8; ++i)
            a[i] += xa * vfa[i] + xb * vfb[i];
    }
    for (; p < end; ++p) {
        int s = g_csrc[p];
        float w = g_cw[p];
        const uint4* r = (const uint4*)(kv + (size_t)s * 512);
        uint4 ku = r[lane], vu = r[32 + lane];
        float kf[8];
        bf8_to_f(ku, kf);
        float t = 0.f;
#pragma unroll
        for (int i = 0; i < 8; ++i) t = fmaf(qv[i], kf[i], t);
#pragma unroll
        for (int o = 8; o; o >>= 1) t += __shfl_xor_sync(0xffffffffu, t, o);
        float x = __expf(fmaf(w, qe, t * scale));
        d += x; cw += x * w;
        float vf[8];
        bf8_to_f(vu, vf);
#pragma unroll
        for (int i = 0; i < 8; ++i) a[i] += x * vf[i];
    }

    float r = d > 0.f ? 1.f / d : 0.f;
    float o8[8];
#pragma unroll
    for (int i = 0; i < 8; ++i) o8[i] = (a[i] + cw * ev[i]) * r;

    if (CONCAT) {
        float sk[8];
        const float* sr = skip + (size_t)n * 256 + lane * 8;
        *(float4*)&sk[0] = *(const float4*)(sr);
        *(float4*)&sk[4] = *(const float4*)(sr + 4);
        __align__(16) __nv_bfloat16 hb[8], lb[8];
#pragma unroll
        for (int i = 0; i < 8; ++i) {
            float o = fmaxf(o8[i] + sk[i], 0.f);
            hb[i] = __float2bfloat16(o);
            lb[i] = __float2bfloat16(o - __bfloat162float(hb[i]));
        }
        *(uint4*)&ohi[(size_t)n * 256 + lane * 8] = *(uint4*)hb;
        *(uint4*)&olo[(size_t)n * 256 + lane * 8] = *(uint4*)lb;
    } else {
        // mean over heads: partner lane = lane ^ 16 holds same in-head channel
        float m[8];
#pragma unroll
        for (int i = 0; i < 8; ++i) {
            float other = __shfl_xor_sync(0xffffffffu, o8[i], 16);
            m[i] = 0.5f * (o8[i] + other);
        }
        if (lane < 16) {
            const float* sr = skip + (size_t)n * 128 + lane * 8;
            float4 s0 = *(const float4*)(sr);
            float4 s1 = *(const float4*)(sr + 4);
            float4 w0 = make_float4(m[0] + s0.x, m[1] + s0.y, m[2] + s0.z, m[3] + s0.w);
            float4 w1 = make_float4(m[4] + s1.x, m[5] + s1.y, m[6] + s1.z, m[7] + s1.w);
            *(float4*)&outf[(size_t)n * 128 + lane * 8]     = w0;
            *(float4*)&outf[(size_t)n * 128 + lane * 8 + 4] = w1;
        }
    }
}

// =============== pooling =======================================================
__global__ __launch_bounds__(256) void pool_zero_kernel(float* __restrict__ out) {
    int i = blockIdx.x * blockDim.x + threadIdx.x;
    if (i < N_GRAPHS * 128) out[i] = 0.f;
    if (i < N_GRAPHS) g_cnt[i] = 0.f;
}

__global__ __launch_bounds__(128) void pool_sum_kernel(
    const int* __restrict__ batch, const float* __restrict__ h,
    float* __restrict__ out)
{
    int n = blockIdx.x;
    int c = threadIdx.x;
    int g = batch[n];
    atomicAdd(&out[(size_t)g * 128 + c], h[(size_t)n * 128 + c]);
    if (c == 0) atomicAdd(&g_cnt[g], 1.f);
}

__global__ __launch_bounds__(256) void pool_div_kernel(float* __restrict__ out) {
    int i = blockIdx.x * blockDim.x + threadIdx.x;
    if (i >= N_GRAPHS * 128) return;
    out[i] /= fmaxf(g_cnt[i >> 7], 1.f);
}

// =============== launch =========================================================
extern "C" void kernel_launch(void* const* d_in, const int* in_sizes, int n_in,
                              void* d_out, int out_size)
{
    const float* x     = (const float*)d_in[0];
    const int*   ei    = (const int*)d_in[1];
    const int*   batch = (const int*)d_in[2];
    const float* ea    = (const float*)d_in[3];
    const float* Wq1 = (const float*)d_in[4];
    const float* bq1 = (const float*)d_in[5];
    const float* Wk1 = (const float*)d_in[6];
    const float* bk1 = (const float*)d_in[7];
    const float* Wv1 = (const float*)d_in[8];
    const float* bv1 = (const float*)d_in[9];
    const float* We1 = (const float*)d_in[10];
    const float* Ws1 = (const float*)d_in[11];
    const float* bs1 = (const float*)d_in[12];
    const float* Wq2 = (const float*)d_in[13];
    const float* bq2 = (const float*)d_in[14];
    const float* Wk2 = (const float*)d_in[15];
    const float* bk2 = (const float*)d_in[16];
    const float* Wv2 = (const float*)d_in[17];
    const float* bv2 = (const float*)d_in[18];
    const float* We2 = (const float*)d_in[19];
    const float* Ws2 = (const float*)d_in[20];
    const float* bs2 = (const float*)d_in[21];
    float* out = (float*)d_out;

    float *pq, *pskip, *ph;
    __nv_bfloat16 *pkv, *pahi, *palo, *pwhi, *pwlo;
    cudaGetSymbolAddress((void**)&pq,    g_q);
    cudaGetSymbolAddress((void**)&pskip, g_skip);
    cudaGetSymbolAddress((void**)&ph,    g_h);
    cudaGetSymbolAddress((void**)&pkv,   g_kv);
    cudaGetSymbolAddress((void**)&pahi,  g_ahi);
    cudaGetSymbolAddress((void**)&palo,  g_alo);
    cudaGetSymbolAddress((void**)&pwhi,  g_whi);
    cudaGetSymbolAddress((void**)&pwlo,  g_wlo);

    const int RT  = (N_NODES + 127) / 128;            // 391 row tiles
    dim3 gm2(RT, 2), gm1(RT, 1);

    const int EB  = (N_EDGES + 255) / 256;
    const int NB  = (N_NODES + 255) / 256;
    const int NWB = (N_NODES + 7) / 8;
    const int PZ  = (N_GRAPHS * 128 + 255) / 256;

    auto cvt = [&](const float* src, __nv_bfloat16* hi, __nv_bfloat16* lo, int cnt) {
        int n4 = cnt / 4;
        cvt_split_kernel<<<(n4 + 255) / 256, 256>>>(src, hi, lo, n4);
    };

    // ---- CSR build (shared by both layers) ----
    zero_wof_kernel<<<NB, 256>>>();
    hist_kernel<<<EB, 256>>>(ei);
    scan_kernel<<<1, 1024>>>();
    csr_scatter_kernel<<<EB, 256>>>(ei, ea);

    // ---- layer 1 (in=128, concat heads) ----
    cvt(x, pahi, palo, N_NODES * 128);
    cvt(Wq1, pwhi,          pwlo,          128 * 256);
    cvt(Wk1, pwhi + 65536,  pwlo + 65536,  128 * 256);
    cvt(Wv1, pwhi + 131072, pwlo + 131072, 128 * 256);
    cvt(Ws1, pwhi + 196608, pwlo + 196608, 128 * 256);
    gemm_mma_kernel<256, 0><<<gm2, 256>>>(pahi, palo, pwhi,          pwlo,          bq1, pq,      nullptr, 256, 0,   128);
    gemm_mma_kernel<256, 1><<<gm2, 256>>>(pahi, palo, pwhi + 65536,  pwlo + 65536,  bk1, nullptr, pkv,     512, 0,   128);
    gemm_mma_kernel<256, 1><<<gm2, 256>>>(pahi, palo, pwhi + 131072, pwlo + 131072, bv1, nullptr, pkv,     512, 256, 128);
    gemm_mma_kernel<256, 0><<<gm2, 256>>>(pahi, palo, pwhi + 196608, pwlo + 196608, bs1, pskip,   nullptr, 256, 0,   128);
    node_attn_kernel<1><<<NWB, 256>>>(pq, pkv, pskip, We1, nullptr, pahi, palo);

    // ---- layer 2 (in=256, mean heads); A = hi/lo written by attn<1> ----
    cvt(Wq2, pwhi,          pwlo,          256 * 256);
    cvt(Wk2, pwhi + 65536,  pwlo + 65536,  256 * 256);
    cvt(Wv2, pwhi + 131072, pwlo + 131072, 256 * 256);
    cvt(Ws2, pwhi + 196608, pwlo + 196608, 256 * 128);
    gemm_mma_kernel<256, 0><<<gm2, 256>>>(pahi, palo, pwhi,          pwlo,          bq2, pq,      nullptr, 256, 0,   256);
    gemm_mma_kernel<256, 1><<<gm2, 256>>>(pahi, palo, pwhi + 65536,  pwlo + 65536,  bk2, nullptr, pkv,     512, 0,   256);
    gemm_mma_kernel<256, 1><<<gm2, 256>>>(pahi, palo, pwhi + 131072, pwlo + 131072, bv2, nullptr, pkv,     512, 256, 256);
    gemm_mma_kernel<128, 0><<<gm1, 256>>>(pahi, palo, pwhi + 196608, pwlo + 196608, bs2, pskip,   nullptr, 128, 0,   256);
    node_attn_kernel<0><<<NWB, 256>>>(pq, pkv, pskip, We2, ph, nullptr, nullptr);

    // ---- global mean pool ----
    pool_zero_kernel<<<PZ, 256>>>(out);
    pool_sum_kernel<<<N_NODES, 128>>>(batch, ph, out);
    pool_div_kernel<<<PZ, 256>>>(out);
}

// round 8
// speedup vs baseline: 5.7277x; 1.1402x over previous
#include <cuda_runtime.h>
#include <cuda_bf16.h>
#include <math.h>
#include <stdint.h>

#define N_NODES  50000
#define N_EDGES  800000
#define N_GRAPHS 2500

// ---------------- scratch (device globals; no allocations allowed) ----------
__device__ __align__(256) float g_q[N_NODES * 256];
__device__ __align__(256) float g_skip[N_NODES * 256];
__device__ __align__(256) float g_h[N_NODES * 128];
__device__ __align__(256) float g_cw[N_EDGES];
__device__ __align__(256) int   g_csrc[N_EDGES];
__device__ __align__(256) int   g_rowptr[N_NODES + 1];
__device__ __align__(256) int   g_wof[N_NODES];
__device__ __align__(256) int   g_bsum[256];
__device__ __align__(256) float g_cnt[N_GRAPHS];
// bf16 operands
__device__ __align__(256) __nv_bfloat16 g_kv[N_NODES * 512];   // [k(256) | v(256)]
__device__ __align__(256) __nv_bfloat16 g_ahi[N_NODES * 256];
__device__ __align__(256) __nv_bfloat16 g_alo[N_NODES * 256];
__device__ __align__(256) __nv_bfloat16 g_whi[262144];
__device__ __align__(256) __nv_bfloat16 g_wlo[262144];

// ================= warp-MMA helpers ==========================================
__device__ __forceinline__ uint32_t smem_u32(const void* p) {
    uint32_t a;
    asm("{ .reg .u64 t; cvta.to.shared.u64 t, %1; cvt.u32.u64 %0, t; }"
        : "=r"(a) : "l"(p));
    return a;
}

__device__ __forceinline__ void ldsm_x4(uint32_t r[4], uint32_t addr) {
    asm volatile("ldmatrix.sync.aligned.m8n8.x4.shared.b16 {%0,%1,%2,%3}, [%4];"
        : "=r"(r[0]), "=r"(r[1]), "=r"(r[2]), "=r"(r[3]) : "r"(addr));
}
__device__ __forceinline__ void ldsm_x4_t(uint32_t r[4], uint32_t addr) {
    asm volatile("ldmatrix.sync.aligned.m8n8.x4.trans.shared.b16 {%0,%1,%2,%3}, [%4];"
        : "=r"(r[0]), "=r"(r[1]), "=r"(r[2]), "=r"(r[3]) : "r"(addr));
}

__device__ __forceinline__ void mma16816(float d[4], const uint32_t a[4],
                                         const uint32_t b[2]) {
    asm volatile(
        "mma.sync.aligned.m16n8k16.row.col.f32.bf16.bf16.f32 "
        "{%0,%1,%2,%3}, {%4,%5,%6,%7}, {%8,%9}, {%0,%1,%2,%3};"
        : "+f"(d[0]), "+f"(d[1]), "+f"(d[2]), "+f"(d[3])
        : "r"(a[0]), "r"(a[1]), "r"(a[2]), "r"(a[3]), "r"(b[0]), "r"(b[1]));
}

__device__ __forceinline__ void cp_async16(uint32_t dst, const void* src, int sz) {
    asm volatile("cp.async.cg.shared.global [%0], [%1], 16, %2;"
        :: "r"(dst), "l"(src), "r"(sz));
}
__device__ __forceinline__ void cp_commit() {
    asm volatile("cp.async.commit_group;" ::: "memory");
}

__device__ __forceinline__ void bf8_to_f(const uint4& u, float* f) {
    float2 p;
    p = __bfloat1622float2(*(const __nv_bfloat162*)&u.x); f[0] = p.x; f[1] = p.y;
    p = __bfloat1622float2(*(const __nv_bfloat162*)&u.y); f[2] = p.x; f[3] = p.y;
    p = __bfloat1622float2(*(const __nv_bfloat162*)&u.z); f[4] = p.x; f[5] = p.y;
    p = __bfloat1622float2(*(const __nv_bfloat162*)&u.w); f[6] = p.x; f[7] = p.y;
}

// =============== fp32 -> bf16 hi/lo split ======================================
__device__ __forceinline__ void split4(float4 v, uint2& hv, uint2& lv) {
    __nv_bfloat16 h0 = __float2bfloat16(v.x);
    __nv_bfloat16 h1 = __float2bfloat16(v.y);
    __nv_bfloat16 h2 = __float2bfloat16(v.z);
    __nv_bfloat16 h3 = __float2bfloat16(v.w);
    __nv_bfloat16 l0 = __float2bfloat16(v.x - __bfloat162float(h0));
    __nv_bfloat16 l1 = __float2bfloat16(v.y - __bfloat162float(h1));
    __nv_bfloat16 l2 = __float2bfloat16(v.z - __bfloat162float(h2));
    __nv_bfloat16 l3 = __float2bfloat16(v.w - __bfloat162float(h3));
    __nv_bfloat162 hp0 = __halves2bfloat162(h0, h1);
    __nv_bfloat162 hp1 = __halves2bfloat162(h2, h3);
    __nv_bfloat162 lp0 = __halves2bfloat162(l0, l1);
    __nv_bfloat162 lp1 = __halves2bfloat162(l2, l3);
    hv = make_uint2(*(uint32_t*)&hp0, *(uint32_t*)&hp1);
    lv = make_uint2(*(uint32_t*)&lp0, *(uint32_t*)&lp1);
}

__global__ __launch_bounds__(256) void cvt_split_kernel(
    const float* __restrict__ src, __nv_bfloat16* __restrict__ hi,
    __nv_bfloat16* __restrict__ lo, int n4)
{
    int i = blockIdx.x * blockDim.x + threadIdx.x;
    if (i >= n4) return;
    uint2 hv, lv;
    split4(((const float4*)src)[i], hv, lv);
    *(uint2*)&hi[i * 4] = hv;
    *(uint2*)&lo[i * 4] = lv;
}

// 4 weight matrices in one launch (grid.y selects matrix)
__global__ __launch_bounds__(256) void cvt_split4_kernel(
    const float* s0, const float* s1, const float* s2, const float* s3,
    __nv_bfloat16* hi, __nv_bfloat16* lo,
    int n4_0, int n4_1, int n4_2, int n4_3)
{
    const float* srcs[4] = {s0, s1, s2, s3};
    int n4s[4]  = {n4_0, n4_1, n4_2, n4_3};
    int offs[4] = {0, 65536, 131072, 196608};
    int m = blockIdx.y;
    int i = blockIdx.x * blockDim.x + threadIdx.x;
    if (i >= n4s[m]) return;
    uint2 hv, lv;
    split4(((const float4*)srcs[m])[i], hv, lv);
    *(uint2*)&hi[offs[m] + i * 4] = hv;
    *(uint2*)&lo[offs[m] + i * 4] = lv;
}

// ================= tensor-core GEMM (cp.async double-buffered) ===============
// smem stage layout (bytes): A_hi[128][40] | A_lo[128][40] | B_hi[32][136] | B_lo[32][136]
#define ST_A_HI 0
#define ST_A_LO 10240
#define ST_B_HI 20480
#define ST_B_LO 29184
#define ST_SIZE 37888
#define GSMEM_TOT (2 * ST_SIZE)

template <int N_OUT, int BF16OUT>
__global__ __launch_bounds__(256) void gemm_mma_kernel(
    const __nv_bfloat16* __restrict__ aHi, const __nv_bfloat16* __restrict__ aLo,
    const __nv_bfloat16* __restrict__ wHi, const __nv_bfloat16* __restrict__ wLo,
    const float* __restrict__ bias, float* __restrict__ Yf,
    __nv_bfloat16* __restrict__ Yb, int ldY, int colOff, int K)
{
    extern __shared__ __align__(16) char smem[];
    const uint32_t sb = smem_u32(smem);

    const int t    = threadIdx.x;
    const int lane = t & 31;
    const int wid  = t >> 5;
    const int wm   = wid & 3;
    const int wn   = wid >> 2;
    const int r0   = blockIdx.x * 128;
    const int c0   = blockIdx.y * 128;

    float acc[2][8][4] = {};

    const int aRow = lane & 15;
    const int aCol = (lane >> 4) * 8;
    const int bK   = lane & 15;
    const int bN   = (lane >> 4) * 8;

    const int nChunks = K >> 5;

    // stage one K-chunk via cp.async
    auto stage = [&](int c, int buf) {
        uint32_t st = sb + buf * ST_SIZE;
        int kc = c << 5;
#pragma unroll
        for (int it = 0; it < 2; ++it) {
            int fid = t + it * 256;             // 0..511
            int row = fid >> 2;
            int col = (fid & 3) * 8;
            int rg  = r0 + row;
            int ok  = (rg < N_NODES) ? 16 : 0;
            int rc  = (rg < N_NODES) ? rg : (N_NODES - 1);
            size_t gidx = (size_t)rc * K + kc + col;
            uint32_t d = st + row * 80 + col * 2;
            cp_async16(d + ST_A_HI, &aHi[gidx], ok);
            cp_async16(d + ST_A_LO, &aLo[gidx], ok);
        }
#pragma unroll
        for (int it = 0; it < 2; ++it) {
            int fid = t + it * 256;
            int kk  = fid >> 4;
            int n   = (fid & 15) * 8;
            size_t gidx = (size_t)(kc + kk) * N_OUT + c0 + n;
            uint32_t d = st + kk * 272 + n * 2;
            cp_async16(d + ST_B_HI, &wHi[gidx], 16);
            cp_async16(d + ST_B_LO, &wLo[gidx], 16);
        }
        cp_commit();
    };

    stage(0, 0);
    for (int c = 0; c < nChunks; ++c) {
        bool more = (c + 1 < nChunks);
        if (more) stage(c + 1, (c + 1) & 1);
        if (more) asm volatile("cp.async.wait_group 1;" ::: "memory");
        else      asm volatile("cp.async.wait_group 0;" ::: "memory");
        __syncthreads();

        uint32_t st = sb + (c & 1) * ST_SIZE;
#pragma unroll
        for (int ks = 0; ks < 2; ++ks) {
            uint32_t aH[2][4], aL[2][4], bf[4][4];
#pragma unroll
            for (int mi = 0; mi < 2; ++mi) {
                uint32_t ar = st + (wm * 32 + mi * 16 + aRow) * 80 + (ks * 16 + aCol) * 2;
                ldsm_x4(aH[mi], ar + ST_A_HI);
                ldsm_x4(aL[mi], ar + ST_A_LO);
            }
#pragma unroll
            for (int pi = 0; pi < 4; ++pi)
                ldsm_x4_t(bf[pi], st + ST_B_HI + (ks * 16 + bK) * 272
                                     + (wn * 64 + pi * 16 + bN) * 2);
#pragma unroll
            for (int mi = 0; mi < 2; ++mi)
#pragma unroll
                for (int pi = 0; pi < 4; ++pi) {
                    mma16816(acc[mi][2 * pi],     aH[mi], &bf[pi][0]);
                    mma16816(acc[mi][2 * pi + 1], aH[mi], &bf[pi][2]);
                }
#pragma unroll
            for (int mi = 0; mi < 2; ++mi)
#pragma unroll
                for (int pi = 0; pi < 4; ++pi) {
                    mma16816(acc[mi][2 * pi],     aL[mi], &bf[pi][0]);
                    mma16816(acc[mi][2 * pi + 1], aL[mi], &bf[pi][2]);
                }
#pragma unroll
            for (int pi = 0; pi < 4; ++pi)
                ldsm_x4_t(bf[pi], st + ST_B_LO + (ks * 16 + bK) * 272
                                     + (wn * 64 + pi * 16 + bN) * 2);
#pragma unroll
            for (int mi = 0; mi < 2; ++mi)
#pragma unroll
                for (int pi = 0; pi < 4; ++pi) {
                    mma16816(acc[mi][2 * pi],     aH[mi], &bf[pi][0]);
                    mma16816(acc[mi][2 * pi + 1], aH[mi], &bf[pi][2]);
                }
        }
        __syncthreads();
    }

#pragma unroll
    for (int mi = 0; mi < 2; ++mi) {
        int rA = r0 + wm * 32 + mi * 16 + (lane >> 2);
        int rB = rA + 8;
#pragma unroll
        for (int ni = 0; ni < 8; ++ni) {
            int cc  = c0 + wn * 64 + ni * 8 + (lane & 3) * 2;
            float2 bv = *(const float2*)&bias[cc];
            float x0 = acc[mi][ni][0] + bv.x, y0 = acc[mi][ni][1] + bv.y;
            float x1 = acc[mi][ni][2] + bv.x, y1 = acc[mi][ni][3] + bv.y;
            int col = colOff + cc;
            if (BF16OUT) {
                if (rA < N_NODES)
                    *(__nv_bfloat162*)&Yb[(size_t)rA * ldY + col] =
                        __floats2bfloat162_rn(x0, y0);
                if (rB < N_NODES)
                    *(__nv_bfloat162*)&Yb[(size_t)rB * ldY + col] =
                        __floats2bfloat162_rn(x1, y1);
            } else {
                if (rA < N_NODES)
                    *(float2*)&Yf[(size_t)rA * ldY + col] = make_float2(x0, y0);
                if (rB < N_NODES)
                    *(float2*)&Yf[(size_t)rB * ldY + col] = make_float2(x1, y1);
            }
        }
    }
}

// =============== CSR build ====================================================
__global__ __launch_bounds__(256) void zero_wof_kernel() {
    int i = blockIdx.x * blockDim.x + threadIdx.x;
    if (i < N_NODES) g_wof[i] = 0;
}

__global__ __launch_bounds__(256) void hist_kernel(const int* __restrict__ ei) {
    int e = blockIdx.x * blockDim.x + threadIdx.x;
    if (e < N_EDGES) atomicAdd(&g_wof[ei[N_EDGES + e]], 1);
}

// hierarchical scan: 196 blocks x 256
__global__ __launch_bounds__(256) void scan1_kernel() {
    __shared__ int sb[2][256];
    int t = threadIdx.x;
    int i = blockIdx.x * 256 + t;
    int v = (i < N_NODES) ? g_wof[i] : 0;
    int pin = 0;
    sb[0][t] = v;
    __syncthreads();
#pragma unroll
    for (int off = 1; off < 256; off <<= 1) {
        int x = sb[pin][t];
        if (t >= off) x += sb[pin][t - off];
        sb[pin ^ 1][t] = x;
        __syncthreads();
        pin ^= 1;
    }
    int incl = sb[pin][t];
    if (i < N_NODES) g_rowptr[i] = incl - v;        // local exclusive
    if (t == 255) g_bsum[blockIdx.x] = incl;        // block total
}

__global__ __launch_bounds__(256) void scan2_kernel(int nblk) {
    __shared__ int sb[2][256];
    int t = threadIdx.x;
    int v = (t < nblk) ? g_bsum[t] : 0;
    int pin = 0;
    sb[0][t] = v;
    __syncthreads();
#pragma unroll
    for (int off = 1; off < 256; off <<= 1) {
        int x = sb[pin][t];
        if (t >= off) x += sb[pin][t - off];
        sb[pin ^ 1][t] = x;
        __syncthreads();
        pin ^= 1;
    }
    if (t < nblk) g_bsum[t] = sb[pin][t] - v;       // block exclusive offset
    if (t == 0) g_rowptr[N_NODES] = N_EDGES;
}

__global__ __launch_bounds__(256) void scan3_kernel() {
    int i = blockIdx.x * 256 + threadIdx.x;
    if (i >= N_NODES) return;
    int r = g_rowptr[i] + g_bsum[blockIdx.x];
    g_rowptr[i] = r;
    g_wof[i]    = r;
}

__global__ __launch_bounds__(256) void csr_scatter_kernel(
    const int* __restrict__ ei, const float* __restrict__ ea)
{
    int e = blockIdx.x * blockDim.x + threadIdx.x;
    if (e >= N_EDGES) return;
    int src = ei[e];
    int dst = ei[N_EDGES + e];
    int pos = atomicAdd(&g_wof[dst], 1);
    g_csrc[pos] = src;
    g_cw[pos]   = ea[e];
}

// =============== per-node attention: bf16 kv gather, half-warp heads ========
template <int CONCAT>
__global__ __launch_bounds__(256, 2) void node_attn_kernel(
    const float* __restrict__ q, const __nv_bfloat16* __restrict__ kv,
    const float* __restrict__ skip, const float* __restrict__ We,
    float* __restrict__ outf, __nv_bfloat16* __restrict__ ohi,
    __nv_bfloat16* __restrict__ olo)
{
    int n = blockIdx.x * 8 + (threadIdx.x >> 5);
    if (n >= N_NODES) return;
    int lane = threadIdx.x & 31;
    int beg = g_rowptr[n], end = g_rowptr[n + 1];

    const float scale = 0.08838834764831845f;   // 1/sqrt(128)

    float qv[8], ev[8];
    {
        const float* qr = q + (size_t)n * 256 + lane * 8;
        *(float4*)&qv[0] = *(const float4*)(qr);
        *(float4*)&qv[4] = *(const float4*)(qr + 4);
        *(float4*)&ev[0] = *(const float4*)(We + lane * 8);
        *(float4*)&ev[4] = *(const float4*)(We + lane * 8 + 4);
    }
    float qe = 0.f;
#pragma unroll
    for (int i = 0; i < 8; ++i) qe = fmaf(qv[i], ev[i], qe);
#pragma unroll
    for (int o = 8; o; o >>= 1) qe += __shfl_xor_sync(0xffffffffu, qe, o);
    qe *= scale;

    float d = 0.f, cw = 0.f;
    float a[8] = {};

    int p = beg;
    for (; p + 1 < end; p += 2) {
        int  sa = g_csrc[p],  sb = g_csrc[p + 1];
        float wa = g_cw[p],   wb = g_cw[p + 1];
        const uint4* ra = (const uint4*)(kv + (size_t)sa * 512);
        const uint4* rb = (const uint4*)(kv + (size_t)sb * 512);
        uint4 kua = ra[lane], kub = rb[lane];
        uint4 vua = ra[32 + lane], vub = rb[32 + lane];

        float kfa[8], kfb[8];
        bf8_to_f(kua, kfa);
        bf8_to_f(kub, kfb);
        float ta = 0.f, tb = 0.f;
#pragma unroll
        for (int i = 0; i < 8; ++i) {
            ta = fmaf(qv[i], kfa[i], ta);
            tb = fmaf(qv[i], kfb[i], tb);
        }
#pragma unroll
        for (int o = 8; o; o >>= 1) {
            ta += __shfl_xor_sync(0xffffffffu, ta, o);
            tb += __shfl_xor_sync(0xffffffffu, tb, o);
        }
        float xa = __expf(fmaf(wa, qe, ta * scale));
        float xb = __expf(fmaf(wb, qe, tb * scale));
        d  += xa + xb;
        cw += xa * wa + xb * wb;
        float vfa[8], vfb[8];
        bf8_to_f(vua, vfa);
        bf8_to_f(vub, vfb);
#pragma unroll
        for (int i = 0; i < 8; ++i)
            a[i] += xa * vfa[i] + xb * vfb[i];
    }
    for (; p < end; ++p) {
        int s = g_csrc[p];
        float w = g_cw[p];
        const uint4* r = (const uint4*)(kv + (size_t)s * 512);
        uint4 ku = r[lane], vu = r[32 + lane];
        float kf[8];
        bf8_to_f(ku, kf);
        float t = 0.f;
#pragma unroll
        for (int i = 0; i < 8; ++i) t = fmaf(qv[i], kf[i], t);
#pragma unroll
        for (int o = 8; o; o >>= 1) t += __shfl_xor_sync(0xffffffffu, t, o);
        float x = __expf(fmaf(w, qe, t * scale));
        d += x; cw += x * w;
        float vf[8];
        bf8_to_f(vu, vf);
#pragma unroll
        for (int i = 0; i < 8; ++i) a[i] += x * vf[i];
    }

    float r = d > 0.f ? 1.f / d : 0.f;
    float o8[8];
#pragma unroll
    for (int i = 0; i < 8; ++i) o8[i] = (a[i] + cw * ev[i]) * r;

    if (CONCAT) {
        float sk[8];
        const float* sr = skip + (size_t)n * 256 + lane * 8;
        *(float4*)&sk[0] = *(const float4*)(sr);
        *(float4*)&sk[4] = *(const float4*)(sr + 4);
        __align__(16) __nv_bfloat16 hb[8], lb[8];
#pragma unroll
        for (int i = 0; i < 8; ++i) {
            float o = fmaxf(o8[i] + sk[i], 0.f);
            hb[i] = __float2bfloat16(o);
            lb[i] = __float2bfloat16(o - __bfloat162float(hb[i]));
        }
        *(uint4*)&ohi[(size_t)n * 256 + lane * 8] = *(uint4*)hb;
        *(uint4*)&olo[(size_t)n * 256 + lane * 8] = *(uint4*)lb;
    } else {
        float m[8];
#pragma unroll
        for (int i = 0; i < 8; ++i) {
            float other = __shfl_xor_sync(0xffffffffu, o8[i], 16);
            m[i] = 0.5f * (o8[i] + other);
        }
        if (lane < 16) {
            const float* sr = skip + (size_t)n * 128 + lane * 8;
            float4 s0 = *(const float4*)(sr);
            float4 s1 = *(const float4*)(sr + 4);
            float4 w0 = make_float4(m[0] + s0.x, m[1] + s0.y, m[2] + s0.z, m[3] + s0.w);
            float4 w1 = make_float4(m[4] + s1.x, m[5] + s1.y, m[6] + s1.z, m[7] + s1.w);
            *(float4*)&outf[(size_t)n * 128 + lane * 8]     = w0;
            *(float4*)&outf[(size_t)n * 128 + lane * 8 + 4] = w1;
        }
    }
}

// =============== pooling =======================================================
__global__ __launch_bounds__(256) void pool_zero_kernel(float* __restrict__ out) {
    int i = blockIdx.x * blockDim.x + threadIdx.x;
    if (i < N_GRAPHS * 128) out[i] = 0.f;
    if (i < N_GRAPHS) g_cnt[i] = 0.f;
}

__global__ __launch_bounds__(128) void pool_sum_kernel(
    const int* __restrict__ batch, const float* __restrict__ h,
    float* __restrict__ out)
{
    int n = blockIdx.x;
    int c = threadIdx.x;
    int g = batch[n];
    atomicAdd(&out[(size_t)g * 128 + c], h[(size_t)n * 128 + c]);
    if (c == 0) atomicAdd(&g_cnt[g], 1.f);
}

__global__ __launch_bounds__(256) void pool_div_kernel(float* __restrict__ out) {
    int i = blockIdx.x * blockDim.x + threadIdx.x;
    if (i >= N_GRAPHS * 128) return;
    out[i] /= fmaxf(g_cnt[i >> 7], 1.f);
}

// =============== launch =========================================================
extern "C" void kernel_launch(void* const* d_in, const int* in_sizes, int n_in,
                              void* d_out, int out_size)
{
    const float* x     = (const float*)d_in[0];
    const int*   ei    = (const int*)d_in[1];
    const int*   batch = (const int*)d_in[2];
    const float* ea    = (const float*)d_in[3];
    const float* Wq1 = (const float*)d_in[4];
    const float* bq1 = (const float*)d_in[5];
    const float* Wk1 = (const float*)d_in[6];
    const float* bk1 = (const float*)d_in[7];
    const float* Wv1 = (const float*)d_in[8];
    const float* bv1 = (const float*)d_in[9];
    const float* We1 = (const float*)d_in[10];
    const float* Ws1 = (const float*)d_in[11];
    const float* bs1 = (const float*)d_in[12];
    const float* Wq2 = (const float*)d_in[13];
    const float* bq2 = (const float*)d_in[14];
    const float* Wk2 = (const float*)d_in[15];
    const float* bk2 = (const float*)d_in[16];
    const float* Wv2 = (const float*)d_in[17];
    const float* bv2 = (const float*)d_in[18];
    const float* We2 = (const float*)d_in[19];
    const float* Ws2 = (const float*)d_in[20];
    const float* bs2 = (const float*)d_in[21];
    float* out = (float*)d_out;

    float *pq, *pskip, *ph;
    __nv_bfloat16 *pkv, *pahi, *palo, *pwhi, *pwlo;
    cudaGetSymbolAddress((void**)&pq,    g_q);
    cudaGetSymbolAddress((void**)&pskip, g_skip);
    cudaGetSymbolAddress((void**)&ph,    g_h);
    cudaGetSymbolAddress((void**)&pkv,   g_kv);
    cudaGetSymbolAddress((void**)&pahi,  g_ahi);
    cudaGetSymbolAddress((void**)&palo,  g_alo);
    cudaGetSymbolAddress((void**)&pwhi,  g_whi);
    cudaGetSymbolAddress((void**)&pwlo,  g_wlo);

    cudaFuncSetAttribute(gemm_mma_kernel<256, 0>,
                         cudaFuncAttributeMaxDynamicSharedMemorySize, GSMEM_TOT);
    cudaFuncSetAttribute(gemm_mma_kernel<256, 1>,
                         cudaFuncAttributeMaxDynamicSharedMemorySize, GSMEM_TOT);
    cudaFuncSetAttribute(gemm_mma_kernel<128, 0>,
                         cudaFuncAttributeMaxDynamicSharedMemorySize, GSMEM_TOT);

    const int RT  = (N_NODES + 127) / 128;            // 391 row tiles
    dim3 gm2(RT, 2), gm1(RT, 1);

    const int EB  = (N_EDGES + 255) / 256;
    const int NB  = (N_NODES + 255) / 256;            // 196
    const int NWB = (N_NODES + 7) / 8;
    const int PZ  = (N_GRAPHS * 128 + 255) / 256;

    // ---- CSR build ----
    zero_wof_kernel<<<NB, 256>>>();
    hist_kernel<<<EB, 256>>>(ei);
    scan1_kernel<<<NB, 256>>>();
    scan2_kernel<<<1, 256>>>(NB);
    scan3_kernel<<<NB, 256>>>();
    csr_scatter_kernel<<<EB, 256>>>(ei, ea);

    // ---- layer 1 (in=128, concat heads) ----
    cvt_split_kernel<<<(N_NODES * 128 / 4 + 255) / 256, 256>>>(x, pahi, palo, N_NODES * 128 / 4);
    cvt_split4_kernel<<<dim3(8192 / 256, 4), 256>>>(Wq1, Wk1, Wv1, Ws1, pwhi, pwlo,
                                                    8192, 8192, 8192, 8192);
    gemm_mma_kernel<256, 0><<<gm2, 256, GSMEM_TOT>>>(pahi, palo, pwhi,          pwlo,          bq1, pq,      nullptr, 256, 0,   128);
    gemm_mma_kernel<256, 1><<<gm2, 256, GSMEM_TOT>>>(pahi, palo, pwhi + 65536,  pwlo + 65536,  bk1, nullptr, pkv,     512, 0,   128);
    gemm_mma_kernel<256, 1><<<gm2, 256, GSMEM_TOT>>>(pahi, palo, pwhi + 131072, pwlo + 131072, bv1, nullptr, pkv,     512, 256, 128);
    gemm_mma_kernel<256, 0><<<gm2, 256, GSMEM_TOT>>>(pahi, palo, pwhi + 196608, pwlo + 196608, bs1, pskip,   nullptr, 256, 0,   128);
    node_attn_kernel<1><<<NWB, 256>>>(pq, pkv, pskip, We1, nullptr, pahi, palo);

    // ---- layer 2 (in=256, mean heads); A = hi/lo written by attn<1> ----
    cvt_split4_kernel<<<dim3(16384 / 256, 4), 256>>>(Wq2, Wk2, Wv2, Ws2, pwhi, pwlo,
                                                     16384, 16384, 16384, 8192);
    gemm_mma_kernel<256, 0><<<gm2, 256, GSMEM_TOT>>>(pahi, palo, pwhi,          pwlo,          bq2, pq,      nullptr, 256, 0,   256);
    gemm_mma_kernel<256, 1><<<gm2, 256, GSMEM_TOT>>>(pahi, palo, pwhi + 65536,  pwlo + 65536,  bk2, nullptr, pkv,     512, 0,   256);
    gemm_mma_kernel<256, 1><<<gm2, 256, GSMEM_TOT>>>(pahi, palo, pwhi + 131072, pwlo + 131072, bv2, nullptr, pkv,     512, 256, 256);
    gemm_mma_kernel<128, 0><<<gm1, 256, GSMEM_TOT>>>(pahi, palo, pwhi + 196608, pwlo + 196608, bs2, pskip,   nullptr, 128, 0,   256);
    node_attn_kernel<0><<<NWB, 256>>>(pq, pkv, pskip, We2, ph, nullptr, nullptr);

    // ---- global mean pool ----
    pool_zero_kernel<<<PZ, 256>>>(out);
    pool_sum_kernel<<<N_NODES, 128>>>(batch, ph, out);
    pool_div_kernel<<<PZ, 256>>>(out);
}